// round 3
// baseline (speedup 1.0000x reference)
#include <cuda_runtime.h>
#include <math.h>

#define BX 2
#define SX 2048
#define FX 512
#define IX 1024
#define KX 3
#define LX 2
#define CX 256

#define PI_F 3.14159265358979323846f

// ---------------- scratch (device globals; no allocation allowed) ------------
__device__ float g_a  [BX*FX*SX];
__device__ float g_b  [BX*FX*SX];
__device__ float g_y1 [BX*IX*SX];
__device__ float g_y2 [BX*IX*SX];
__device__ float g_d  [BX*FX*SX];
__device__ float g_sc [BX*FX*SX];
__device__ float g_sh [BX*FX*SX];
__device__ float g_str[BX*2*FX*SX];
__device__ float g_log[BX*CX*SX];
__device__ float g_fe [FX];
__device__ float g_nll[BX*SX];

// ---------------- feature embedding ------------------------------------------
__global__ void fe_kernel() {
    int f = blockIdx.x * blockDim.x + threadIdx.x;
    if (f < FX) {
        float ff = (float)f + 1.0f;
        float additive = fmodf(ff, 2.0f);
        float g = (ff - additive) * 0.5f;
        g = g * (8.0f / (float)FX) - logf((float)CX / (2.0f * PI_F));
        g_fe[f] = expf(g) + additive * PI_F;
    }
}

// ---------------- embedding gather -------------------------------------------
__global__ void embed_kernel(const int* __restrict__ inp,
                             const float* __restrict__ emb) {
    size_t idx = (size_t)blockIdx.x * blockDim.x + threadIdx.x;
    if (idx >= (size_t)BX * FX * SX) return;
    int s = (int)(idx % SX);
    int f = (int)((idx / SX) % FX);
    int b = (int)(idx / ((size_t)SX * FX));
    int tok = inp[b * SX + s];
    g_a[idx] = emb[(size_t)tok * (2 * FX) + f];
    g_b[idx] = emb[(size_t)tok * (2 * FX) + FX + f];
}

// ---------------- generic conv-GEMM ------------------------------------------
// Y[b,m,n] = act( sum_t sum_k A[m, k, t] * X[b, k, n + t - (TAPS-1)] (+vec[k]) ) (+bias[m])
// A layout: A[m*Kd*TAPS + k*TAPS + t]
template <int TAPS, bool RELU, bool ADDVEC, bool BIAS>
__global__ void convgemm(const float* __restrict__ A,
                         const float* __restrict__ X,
                         float* __restrict__ Y,
                         const float* __restrict__ vec,
                         const float* __restrict__ bias,
                         int M, int Kd, int N) {
    __shared__ float As[16][65];
    __shared__ __align__(16) float Xs[16][64];

    int b  = blockIdx.z;
    int m0 = blockIdx.y * 64;
    int n0 = blockIdx.x * 64;
    int tid = threadIdx.x;      // 256 threads
    int tx = tid & 15;          // column group (4 cols each)
    int ty = tid >> 4;          // row group (4 rows each)

    float acc[4][4];
#pragma unroll
    for (int i = 0; i < 4; i++)
#pragma unroll
        for (int j = 0; j < 4; j++) acc[i][j] = 0.0f;

    for (int t = 0; t < TAPS; ++t) {
        int shift = t - (TAPS - 1);
        for (int k0 = 0; k0 < Kd; k0 += 16) {
            // load A tile (16 x 64), global reads ~coalesced along k
#pragma unroll
            for (int i = 0; i < 4; i++) {
                int idx = tid + i * 256;
                int mm = idx >> 4;
                int kk = idx & 15;
                As[kk][mm] = A[(size_t)(m0 + mm) * Kd * TAPS + (size_t)(k0 + kk) * TAPS + t];
            }
            // load X tile (16 x 64) with causal shift
#pragma unroll
            for (int i = 0; i < 4; i++) {
                int idx = tid + i * 256;
                int kk = idx >> 6;
                int nn = idx & 63;
                int col = n0 + nn + shift;
                float v = 0.0f;
                if (col >= 0) {
                    v = X[((size_t)b * Kd + (k0 + kk)) * N + col];
                    if (ADDVEC) v += vec[k0 + kk];
                }
                Xs[kk][nn] = v;
            }
            __syncthreads();
#pragma unroll
            for (int kk = 0; kk < 16; ++kk) {
                float av[4];
#pragma unroll
                for (int i = 0; i < 4; i++) av[i] = As[kk][ty * 4 + i];
                float4 xq = *(const float4*)&Xs[kk][tx * 4];
                float xv[4] = {xq.x, xq.y, xq.z, xq.w};
#pragma unroll
                for (int i = 0; i < 4; i++)
#pragma unroll
                    for (int j = 0; j < 4; j++) acc[i][j] += av[i] * xv[j];
            }
            __syncthreads();
        }
    }

#pragma unroll
    for (int i = 0; i < 4; i++) {
        int m = m0 + ty * 4 + i;
        float4 v = make_float4(acc[i][0], acc[i][1], acc[i][2], acc[i][3]);
        if (BIAS) {
            float bi = bias[m];
            v.x += bi; v.y += bi; v.z += bi; v.w += bi;
        }
        if (RELU) {
            v.x = fmaxf(v.x, 0.0f); v.y = fmaxf(v.y, 0.0f);
            v.z = fmaxf(v.z, 0.0f); v.w = fmaxf(v.w, 0.0f);
        }
        *(float4*)&Y[((size_t)b * M + m) * N + n0 + tx * 4] = v;
    }
}

// ---------------- combine: cumsum over F, norm, EMA update -------------------
__global__ void combine_kernel() {
    int bs = blockIdx.x;            // B*S blocks
    int b = bs >> 11;               // S = 2048
    int s = bs & 2047;
    int f = threadIdx.x;            // 512 threads
    size_t idx = ((size_t)b * FX + f) * SX + s;

    float dv  = g_d[idx];
    float scv = g_sc[idx];
    float shv = g_sh[idx];

    int lane = f & 31, wid = f >> 5;

    // inclusive scan over f (warp scan + warp-prefix scan)
    float v = dv;
#pragma unroll
    for (int o = 1; o < 32; o <<= 1) {
        float t2 = __shfl_up_sync(0xffffffffu, v, o);
        if (lane >= o) v += t2;
    }
    __shared__ float wtot[16], wpref[16], red[16];
    __shared__ float bc[2];
    if (lane == 31) wtot[wid] = v;
    __syncthreads();
    if (f < 16) {
        float w = wtot[f];
#pragma unroll
        for (int o = 1; o < 16; o <<= 1) {
            float t2 = __shfl_up_sync(0x0000ffffu, w, o);
            if (f >= o) w += t2;
        }
        wpref[f] = w;
    }
    __syncthreads();
    float cum = v + (wid ? wpref[wid - 1] : 0.0f);

    float val = cum * (1.0f / (float)(s + 1)) * scv + shv;

    // mean over F (deterministic: serial over 16 warp partials)
    float r = val;
#pragma unroll
    for (int o = 16; o > 0; o >>= 1) r += __shfl_xor_sync(0xffffffffu, r, o);
    if (lane == 0) red[wid] = r;
    __syncthreads();
    if (f == 0) {
        float t2 = 0.0f;
        for (int i = 0; i < 16; i++) t2 += red[i];
        bc[0] = t2 * (1.0f / (float)FX);
    }
    __syncthreads();
    float vc = val - bc[0];

    // sum of squares
    float q = vc * vc;
#pragma unroll
    for (int o = 16; o > 0; o >>= 1) q += __shfl_xor_sync(0xffffffffu, q, o);
    __syncthreads();
    if (lane == 0) red[wid] = q;
    __syncthreads();
    if (f == 0) {
        float t2 = 0.0f;
        for (int i = 0; i < 16; i++) t2 += red[i];
        // denom = ||x|| * F^{-1/2} + 1e-5
        bc[1] = sqrtf(t2) * rsqrtf((float)FX) + 1e-5f;
    }
    __syncthreads();

    const float INIT_SCALE = 0.7071067811865476f;   // L^{-1/2}
    const float BETA = 0.99f;
    float cell = vc / bc[1] * INIT_SCALE;
    float aold = g_a[idx];
    float c = BETA * aold + (1.0f - BETA) * cell;
    g_a[idx] = c;
    g_b[idx] += c;
}

// ---------------- build streams = concat([a,b], ch) --------------------------
__global__ void streams_kernel() {
    size_t idx = (size_t)blockIdx.x * blockDim.x + threadIdx.x;
    if (idx >= (size_t)BX * FX * SX) return;
    int s = (int)(idx % SX);
    int f = (int)((idx / SX) % FX);
    int b = (int)(idx / ((size_t)SX * FX));
    g_str[((size_t)b * 2 * FX + f) * SX + s]      = g_a[idx];
    g_str[((size_t)b * 2 * FX + FX + f) * SX + s] = g_b[idx];
}

// ---------------- per-position NLL -------------------------------------------
__global__ void nll_kernel(const int* __restrict__ tgt) {
    int bs = blockIdx.x;            // B*S blocks
    int b = bs >> 11;
    int s = bs & 2047;
    int c = threadIdx.x;            // 256 threads
    float x = g_log[((size_t)b * CX + c) * SX + s];

    int lane = c & 31, wid = c >> 5;
    __shared__ float red[8];
    __shared__ float bc[2];
    __shared__ float tval;

    // max
    float m = x;
#pragma unroll
    for (int o = 16; o > 0; o >>= 1) m = fmaxf(m, __shfl_xor_sync(0xffffffffu, m, o));
    if (lane == 0) red[wid] = m;
    __syncthreads();
    if (c == 0) {
        float t2 = red[0];
        for (int i = 1; i < 8; i++) t2 = fmaxf(t2, red[i]);
        bc[0] = t2;
    }
    __syncthreads();
    float e = expf(x - bc[0]);
#pragma unroll
    for (int o = 16; o > 0; o >>= 1) e += __shfl_xor_sync(0xffffffffu, e, o);
    __syncthreads();
    if (lane == 0) red[wid] = e;
    int tv = tgt[b * SX + s];
    if (c == tv) tval = x;
    __syncthreads();
    if (c == 0) {
        float t2 = 0.0f;
        for (int i = 0; i < 8; i++) t2 += red[i];
        float lse = bc[0] + logf(t2);
        g_nll[bs] = lse - tval;
    }
}

// ---------------- deterministic final mean -----------------------------------
__global__ void reduce_kernel(float* __restrict__ out) {
    __shared__ float sh[1024];
    int t = threadIdx.x;
    float s = 0.0f;
    for (int i = t; i < BX * SX; i += 1024) s += g_nll[i];
    sh[t] = s;
    __syncthreads();
    for (int o = 512; o > 0; o >>= 1) {
        if (t < o) sh[t] += sh[t + o];
        __syncthreads();
    }
    if (t == 0) out[0] = sh[0] / (float)(BX * SX);
}

// ---------------- host orchestration -----------------------------------------
extern "C" void kernel_launch(void* const* d_in, const int* in_sizes, int n_in,
                              void* d_out, int out_size) {
    const int*   inp   = (const int*)d_in[0];
    const int*   tgt   = (const int*)d_in[1];
    const float* emb   = (const float*)d_in[2];
    const float* w0s   = (const float*)d_in[3];
    const float* w1s   = (const float*)d_in[4];
    const float* w2s   = (const float*)d_in[5];
    const float* out_w = (const float*)d_in[6];
    const float* out_b = (const float*)d_in[7];
    float* out = (float*)d_out;

    float *pa, *pb, *py1, *py2, *pd, *psc, *psh, *pstr, *plog, *pfe;
    cudaGetSymbolAddress((void**)&pa,  g_a);
    cudaGetSymbolAddress((void**)&pb,  g_b);
    cudaGetSymbolAddress((void**)&py1, g_y1);
    cudaGetSymbolAddress((void**)&py2, g_y2);
    cudaGetSymbolAddress((void**)&pd,  g_d);
    cudaGetSymbolAddress((void**)&psc, g_sc);
    cudaGetSymbolAddress((void**)&psh, g_sh);
    cudaGetSymbolAddress((void**)&pstr, g_str);
    cudaGetSymbolAddress((void**)&plog, g_log);
    cudaGetSymbolAddress((void**)&pfe, g_fe);

    fe_kernel<<<1, 512>>>();
    {
        size_t n = (size_t)BX * FX * SX;
        embed_kernel<<<(unsigned)((n + 255) / 256), 256>>>(inp, emb);
    }

    float* outs[3] = {pd, psc, psh};

    for (int l = 0; l < LX; ++l) {
        for (int m = 0; m < 3; ++m) {
            const float* W0 = w0s + (size_t)(l * 3 + m) * IX * FX;
            const float* W1 = w1s + (size_t)(l * 3 + m) * IX * IX * KX;
            const float* W2 = w2s + (size_t)(l * 3 + m) * FX * IX;

            dim3 gridI(SX / 64, IX / 64, BX);
            dim3 gridF(SX / 64, FX / 64, BX);
            // conv0: F->I pointwise, input = b + fe, relu
            convgemm<1, true, true, false><<<gridI, 256>>>(W0, pb, py1, pfe, nullptr, IX, FX, SX);
            // conv1: I->I causal k=3, relu
            convgemm<3, true, false, false><<<gridI, 256>>>(W1, py1, py2, nullptr, nullptr, IX, IX, SX);
            // conv2: I->F pointwise
            convgemm<1, false, false, false><<<gridF, 256>>>(W2, py2, outs[m], nullptr, nullptr, FX, IX, SX);
        }
        combine_kernel<<<BX * SX, 512>>>();
    }

    {
        size_t n = (size_t)BX * FX * SX;
        streams_kernel<<<(unsigned)((n + 255) / 256), 256>>>();
    }
    {
        dim3 gridC(SX / 64, CX / 64, BX);
        convgemm<1, false, false, true><<<gridC, 256>>>(out_w, pstr, plog, nullptr, out_b, CX, 2 * FX, SX);
    }
    nll_kernel<<<BX * SX, 256>>>(tgt);
    reduce_kernel<<<1, 1024>>>(out);
}

// round 7
// speedup vs baseline: 2.6573x; 2.6573x over previous
#include <cuda_runtime.h>
#include <math.h>
#include <stdint.h>

#define BX 2
#define SX 2048
#define FX 512
#define IX 1024
#define KX 3
#define LX 2
#define CX 256

#define PI_F 3.14159265358979323846f

// ---------------- scratch (device globals; no allocation allowed) ------------
__device__ float g_a  [BX*FX*SX];
__device__ float g_b  [BX*FX*SX];
__device__ float g_y1 [BX*IX*SX];
__device__ float g_y2 [BX*IX*SX];
__device__ float g_d  [BX*FX*SX];
__device__ float g_sc [BX*FX*SX];
__device__ float g_sh [BX*FX*SX];
__device__ float g_str[BX*2*FX*SX];
__device__ float g_log[BX*CX*SX];
__device__ float g_fe [FX];
__device__ float g_nll[BX*SX];

// ---------------- feature embedding ------------------------------------------
__global__ void fe_kernel() {
    int f = blockIdx.x * blockDim.x + threadIdx.x;
    if (f < FX) {
        float ff = (float)f + 1.0f;
        float additive = fmodf(ff, 2.0f);
        float g = (ff - additive) * 0.5f;
        g = g * (8.0f / (float)FX) - logf((float)CX / (2.0f * PI_F));
        g_fe[f] = expf(g) + additive * PI_F;
    }
}

// ---------------- embedding gather -------------------------------------------
__global__ void embed_kernel(const int* __restrict__ inp,
                             const float* __restrict__ emb) {
    size_t idx = (size_t)blockIdx.x * blockDim.x + threadIdx.x;
    if (idx >= (size_t)BX * FX * SX) return;
    int s = (int)(idx % SX);
    int f = (int)((idx / SX) % FX);
    int b = (int)(idx / ((size_t)SX * FX));
    int tok = inp[b * SX + s];
    g_a[idx] = emb[(size_t)tok * (2 * FX) + f];
    g_b[idx] = emb[(size_t)tok * (2 * FX) + FX + f];
}

// ================= tf32 tensor-core conv-GEMM ================================
// Y[b,m,n] = act( sum_{k'} A'[m,k'] * X'[k', n] )
//   A' = weights flattened row-major [M, Kd*TAPS]  (k' = k*TAPS + t)
//   X'[k',n] = X[b, k'/TAPS, n + (k'%TAPS) - (TAPS-1)]  (causal zero pad)
// Block tile 128(M) x 128(N), K-chunk 32. 8 warps: 2(M) x 4(N), warp 64x32.
// mma.sync.m16n8k8 tf32, fp32 accumulate.

__device__ __forceinline__ uint32_t f2tf32(float x) {
    uint32_t r;
    asm("cvt.rna.tf32.f32 %0, %1;" : "=r"(r) : "f"(x));
    return r;
}

__device__ __forceinline__ void mma_tf32(float* c, const uint32_t* a, const uint32_t* b) {
    asm volatile(
        "mma.sync.aligned.m16n8k8.row.col.f32.tf32.tf32.f32 "
        "{%0,%1,%2,%3}, {%4,%5,%6,%7}, {%8,%9}, {%0,%1,%2,%3};"
        : "+f"(c[0]), "+f"(c[1]), "+f"(c[2]), "+f"(c[3])
        : "r"(a[0]), "r"(a[1]), "r"(a[2]), "r"(a[3]), "r"(b[0]), "r"(b[1]));
}

template <int TAPS, bool RELU, bool ADDVEC, bool BIAS>
__global__ __launch_bounds__(256)
void mmconv(const float* __restrict__ A,
            const float* __restrict__ X,
            float* __restrict__ Y,
            const float* __restrict__ vec,
            const float* __restrict__ bias,
            int M, int Kd, int N) {
    __shared__ uint32_t As[128][36];   // [m][k] pad 36 (144B rows)
    __shared__ uint32_t Xs[32][132];   // [k'][n] pad 132 (528B rows)

    const int Kp = Kd * TAPS;
    const int b  = blockIdx.z;
    const int m0 = blockIdx.y * 128;
    const int n0 = blockIdx.x * 128;
    const int tid  = threadIdx.x;
    const int lane = tid & 31;
    const int w    = tid >> 5;
    const int wM   = (w >> 2) * 64;    // warp M offset in tile
    const int wN   = (w & 3) * 32;     // warp N offset in tile
    const int g    = lane >> 2;        // group id (row within 8)
    const int tig  = lane & 3;         // thread in group (k / col pair)

    float c[4][4][4];
#pragma unroll
    for (int i = 0; i < 4; i++)
#pragma unroll
        for (int j = 0; j < 4; j++)
#pragma unroll
            for (int q = 0; q < 4; q++) c[i][j][q] = 0.0f;

    for (int k0 = 0; k0 < Kp; k0 += 32) {
        // ---- load A tile: 128 x 32, contiguous row-major, float4 ----
#pragma unroll
        for (int q = 0; q < 4; q++) {
            int idx = tid + q * 256;           // 0..1023
            int row = idx >> 3;                // 0..127
            int c4  = (idx & 7) * 4;           // 0..28
            float4 v = *(const float4*)&A[(size_t)(m0 + row) * Kp + k0 + c4];
            As[row][c4 + 0] = f2tf32(v.x);
            As[row][c4 + 1] = f2tf32(v.y);
            As[row][c4 + 2] = f2tf32(v.z);
            As[row][c4 + 3] = f2tf32(v.w);
        }
        // ---- load X tile: 32 x 128 ----
        if (TAPS == 1) {
#pragma unroll
            for (int q = 0; q < 4; q++) {
                int idx = tid + q * 256;       // 0..1023
                int row = idx >> 5;            // 0..31 (= k)
                int c4  = (idx & 31) * 4;      // 0..124
                float4 v = *(const float4*)&X[((size_t)b * Kd + k0 + row) * N + n0 + c4];
                if (ADDVEC) {
                    float fv = vec[k0 + row];
                    v.x += fv; v.y += fv; v.z += fv; v.w += fv;
                }
                Xs[row][c4 + 0] = f2tf32(v.x);
                Xs[row][c4 + 1] = f2tf32(v.y);
                Xs[row][c4 + 2] = f2tf32(v.z);
                Xs[row][c4 + 3] = f2tf32(v.w);
            }
        } else {
#pragma unroll
            for (int q = 0; q < 16; q++) {
                int idx = tid + q * 256;       // 0..4095
                int row = idx >> 7;            // 0..31
                int cc  = idx & 127;
                int kp  = k0 + row;
                int k   = kp / TAPS;
                int t   = kp - k * TAPS;
                int col = n0 + cc + t - (TAPS - 1);
                float v = (col >= 0) ? X[((size_t)b * Kd + k) * N + col] : 0.0f;
                Xs[row][cc] = f2tf32(v);
            }
        }
        __syncthreads();

        // ---- compute: 4 k-steps of 8 ----
#pragma unroll
        for (int kk = 0; kk < 4; kk++) {
            uint32_t af[4][4], bf[4][2];
            int kb = kk * 8 + tig;
#pragma unroll
            for (int i = 0; i < 4; i++) {
                int m = wM + i * 16 + g;
                af[i][0] = As[m][kb];
                af[i][1] = As[m + 8][kb];
                af[i][2] = As[m][kb + 4];
                af[i][3] = As[m + 8][kb + 4];
            }
#pragma unroll
            for (int j = 0; j < 4; j++) {
                int n = wN + j * 8 + g;
                bf[j][0] = Xs[kk * 8 + tig][n];
                bf[j][1] = Xs[kk * 8 + tig + 4][n];
            }
#pragma unroll
            for (int i = 0; i < 4; i++)
#pragma unroll
                for (int j = 0; j < 4; j++)
                    mma_tf32(c[i][j], af[i], bf[j]);
        }
        __syncthreads();
    }

    // ---- epilogue ----
#pragma unroll
    for (int i = 0; i < 4; i++) {
        int m = m0 + wM + i * 16 + g;
        float bi0 = BIAS ? bias[m] : 0.0f;
        float bi1 = BIAS ? bias[m + 8] : 0.0f;
#pragma unroll
        for (int j = 0; j < 4; j++) {
            int n = n0 + wN + j * 8 + 2 * tig;
            float2 v0 = make_float2(c[i][j][0] + bi0, c[i][j][1] + bi0);
            float2 v1 = make_float2(c[i][j][2] + bi1, c[i][j][3] + bi1);
            if (RELU) {
                v0.x = fmaxf(v0.x, 0.0f); v0.y = fmaxf(v0.y, 0.0f);
                v1.x = fmaxf(v1.x, 0.0f); v1.y = fmaxf(v1.y, 0.0f);
            }
            *(float2*)&Y[((size_t)b * M + m) * N + n]     = v0;
            *(float2*)&Y[((size_t)b * M + m + 8) * N + n] = v1;
        }
    }
}

// ---------------- fp32 SIMT conv-GEMM (kept for the logits layer) ------------
template <int TAPS, bool RELU, bool ADDVEC, bool BIAS>
__global__ void convgemm(const float* __restrict__ A,
                         const float* __restrict__ X,
                         float* __restrict__ Y,
                         const float* __restrict__ vec,
                         const float* __restrict__ bias,
                         int M, int Kd, int N) {
    __shared__ float As[16][65];
    __shared__ __align__(16) float Xs[16][64];

    int b  = blockIdx.z;
    int m0 = blockIdx.y * 64;
    int n0 = blockIdx.x * 64;
    int tid = threadIdx.x;
    int tx = tid & 15;
    int ty = tid >> 4;

    float acc[4][4];
#pragma unroll
    for (int i = 0; i < 4; i++)
#pragma unroll
        for (int j = 0; j < 4; j++) acc[i][j] = 0.0f;

    for (int t = 0; t < TAPS; ++t) {
        int shift = t - (TAPS - 1);
        for (int k0 = 0; k0 < Kd; k0 += 16) {
#pragma unroll
            for (int i = 0; i < 4; i++) {
                int idx = tid + i * 256;
                int mm = idx >> 4;
                int kk = idx & 15;
                As[kk][mm] = A[(size_t)(m0 + mm) * Kd * TAPS + (size_t)(k0 + kk) * TAPS + t];
            }
#pragma unroll
            for (int i = 0; i < 4; i++) {
                int idx = tid + i * 256;
                int kk = idx >> 6;
                int nn = idx & 63;
                int col = n0 + nn + shift;
                float v = 0.0f;
                if (col >= 0) {
                    v = X[((size_t)b * Kd + (k0 + kk)) * N + col];
                    if (ADDVEC) v += vec[k0 + kk];
                }
                Xs[kk][nn] = v;
            }
            __syncthreads();
#pragma unroll
            for (int kk = 0; kk < 16; ++kk) {
                float av[4];
#pragma unroll
                for (int i = 0; i < 4; i++) av[i] = As[kk][ty * 4 + i];
                float4 xq = *(const float4*)&Xs[kk][tx * 4];
                float xv[4] = {xq.x, xq.y, xq.z, xq.w};
#pragma unroll
                for (int i = 0; i < 4; i++)
#pragma unroll
                    for (int j = 0; j < 4; j++) acc[i][j] += av[i] * xv[j];
            }
            __syncthreads();
        }
    }

#pragma unroll
    for (int i = 0; i < 4; i++) {
        int m = m0 + ty * 4 + i;
        float4 v = make_float4(acc[i][0], acc[i][1], acc[i][2], acc[i][3]);
        if (BIAS) {
            float bi = bias[m];
            v.x += bi; v.y += bi; v.z += bi; v.w += bi;
        }
        if (RELU) {
            v.x = fmaxf(v.x, 0.0f); v.y = fmaxf(v.y, 0.0f);
            v.z = fmaxf(v.z, 0.0f); v.w = fmaxf(v.w, 0.0f);
        }
        *(float4*)&Y[((size_t)b * M + m) * N + n0 + tx * 4] = v;
    }
}

// ---------------- combine: cumsum over F, norm, EMA update -------------------
__global__ void combine_kernel() {
    int bs = blockIdx.x;
    int b = bs >> 11;
    int s = bs & 2047;
    int f = threadIdx.x;
    size_t idx = ((size_t)b * FX + f) * SX + s;

    float dv  = g_d[idx];
    float scv = g_sc[idx];
    float shv = g_sh[idx];

    int lane = f & 31, wid = f >> 5;

    float v = dv;
#pragma unroll
    for (int o = 1; o < 32; o <<= 1) {
        float t2 = __shfl_up_sync(0xffffffffu, v, o);
        if (lane >= o) v += t2;
    }
    __shared__ float wtot[16], wpref[16], red[16];
    __shared__ float bc[2];
    if (lane == 31) wtot[wid] = v;
    __syncthreads();
    if (f < 16) {
        float w = wtot[f];
#pragma unroll
        for (int o = 1; o < 16; o <<= 1) {
            float t2 = __shfl_up_sync(0x0000ffffu, w, o);
            if (f >= o) w += t2;
        }
        wpref[f] = w;
    }
    __syncthreads();
    float cum = v + (wid ? wpref[wid - 1] : 0.0f);

    float val = cum * (1.0f / (float)(s + 1)) * scv + shv;

    float r = val;
#pragma unroll
    for (int o = 16; o > 0; o >>= 1) r += __shfl_xor_sync(0xffffffffu, r, o);
    if (lane == 0) red[wid] = r;
    __syncthreads();
    if (f == 0) {
        float t2 = 0.0f;
        for (int i = 0; i < 16; i++) t2 += red[i];
        bc[0] = t2 * (1.0f / (float)FX);
    }
    __syncthreads();
    float vc = val - bc[0];

    float q = vc * vc;
#pragma unroll
    for (int o = 16; o > 0; o >>= 1) q += __shfl_xor_sync(0xffffffffu, q, o);
    __syncthreads();
    if (lane == 0) red[wid] = q;
    __syncthreads();
    if (f == 0) {
        float t2 = 0.0f;
        for (int i = 0; i < 16; i++) t2 += red[i];
        bc[1] = sqrtf(t2) * rsqrtf((float)FX) + 1e-5f;
    }
    __syncthreads();

    const float INIT_SCALE = 0.7071067811865476f;
    const float BETA = 0.99f;
    float cell = vc / bc[1] * INIT_SCALE;
    float aold = g_a[idx];
    float cnew = BETA * aold + (1.0f - BETA) * cell;
    g_a[idx] = cnew;
    g_b[idx] += cnew;
}

// ---------------- build streams = concat([a,b], ch) --------------------------
__global__ void streams_kernel() {
    size_t idx = (size_t)blockIdx.x * blockDim.x + threadIdx.x;
    if (idx >= (size_t)BX * FX * SX) return;
    int s = (int)(idx % SX);
    int f = (int)((idx / SX) % FX);
    int b = (int)(idx / ((size_t)SX * FX));
    g_str[((size_t)b * 2 * FX + f) * SX + s]      = g_a[idx];
    g_str[((size_t)b * 2 * FX + FX + f) * SX + s] = g_b[idx];
}

// ---------------- per-position NLL -------------------------------------------
__global__ void nll_kernel(const int* __restrict__ tgt) {
    int bs = blockIdx.x;
    int b = bs >> 11;
    int s = bs & 2047;
    int c = threadIdx.x;
    float x = g_log[((size_t)b * CX + c) * SX + s];

    int lane = c & 31, wid = c >> 5;
    __shared__ float red[8];
    __shared__ float bc[2];
    __shared__ float tval;

    float m = x;
#pragma unroll
    for (int o = 16; o > 0; o >>= 1) m = fmaxf(m, __shfl_xor_sync(0xffffffffu, m, o));
    if (lane == 0) red[wid] = m;
    __syncthreads();
    if (c == 0) {
        float t2 = red[0];
        for (int i = 1; i < 8; i++) t2 = fmaxf(t2, red[i]);
        bc[0] = t2;
    }
    __syncthreads();
    float e = expf(x - bc[0]);
#pragma unroll
    for (int o = 16; o > 0; o >>= 1) e += __shfl_xor_sync(0xffffffffu, e, o);
    __syncthreads();
    if (lane == 0) red[wid] = e;
    int tv = tgt[b * SX + s];
    if (c == tv) tval = x;
    __syncthreads();
    if (c == 0) {
        float t2 = 0.0f;
        for (int i = 0; i < 8; i++) t2 += red[i];
        float lse = bc[0] + logf(t2);
        g_nll[bs] = lse - tval;
    }
}

// ---------------- deterministic final mean -----------------------------------
__global__ void reduce_kernel(float* __restrict__ out) {
    __shared__ float sh[1024];
    int t = threadIdx.x;
    float s = 0.0f;
    for (int i = t; i < BX * SX; i += 1024) s += g_nll[i];
    sh[t] = s;
    __syncthreads();
    for (int o = 512; o > 0; o >>= 1) {
        if (t < o) sh[t] += sh[t + o];
        __syncthreads();
    }
    if (t == 0) out[0] = sh[0] / (float)(BX * SX);
}

// ---------------- host orchestration -----------------------------------------
extern "C" void kernel_launch(void* const* d_in, const int* in_sizes, int n_in,
                              void* d_out, int out_size) {
    const int*   inp   = (const int*)d_in[0];
    const int*   tgt   = (const int*)d_in[1];
    const float* emb   = (const float*)d_in[2];
    const float* w0s   = (const float*)d_in[3];
    const float* w1s   = (const float*)d_in[4];
    const float* w2s   = (const float*)d_in[5];
    const float* out_w = (const float*)d_in[6];
    const float* out_b = (const float*)d_in[7];
    float* out = (float*)d_out;

    float *pa, *pb, *py1, *py2, *pd, *psc, *psh, *pstr, *plog, *pfe;
    cudaGetSymbolAddress((void**)&pa,  g_a);
    cudaGetSymbolAddress((void**)&pb,  g_b);
    cudaGetSymbolAddress((void**)&py1, g_y1);
    cudaGetSymbolAddress((void**)&py2, g_y2);
    cudaGetSymbolAddress((void**)&pd,  g_d);
    cudaGetSymbolAddress((void**)&psc, g_sc);
    cudaGetSymbolAddress((void**)&psh, g_sh);
    cudaGetSymbolAddress((void**)&pstr, g_str);
    cudaGetSymbolAddress((void**)&plog, g_log);
    cudaGetSymbolAddress((void**)&pfe, g_fe);

    fe_kernel<<<1, 512>>>();
    {
        size_t n = (size_t)BX * FX * SX;
        embed_kernel<<<(unsigned)((n + 255) / 256), 256>>>(inp, emb);
    }

    float* outs[3] = {pd, psc, psh};

    for (int l = 0; l < LX; ++l) {
        for (int m = 0; m < 3; ++m) {
            const float* W0 = w0s + (size_t)(l * 3 + m) * IX * FX;
            const float* W1 = w1s + (size_t)(l * 3 + m) * IX * IX * KX;
            const float* W2 = w2s + (size_t)(l * 3 + m) * FX * IX;

            dim3 gridI(SX / 128, IX / 128, BX);   // 16 x 8 x 2
            dim3 gridF(SX / 128, FX / 128, BX);   // 16 x 4 x 2
            // conv0: F->I pointwise, input = b + fe, relu
            mmconv<1, true, true, false><<<gridI, 256>>>(W0, pb, py1, pfe, nullptr, IX, FX, SX);
            // conv1: I->I causal k=3, relu
            mmconv<3, true, false, false><<<gridI, 256>>>(W1, py1, py2, nullptr, nullptr, IX, IX, SX);
            // conv2: I->F pointwise
            mmconv<1, false, false, false><<<gridF, 256>>>(W2, py2, outs[m], nullptr, nullptr, FX, IX, SX);
        }
        combine_kernel<<<BX * SX, 512>>>();
    }

    {
        size_t n = (size_t)BX * FX * SX;
        streams_kernel<<<(unsigned)((n + 255) / 256), 256>>>();
    }
    {
        dim3 gridC(SX / 64, CX / 64, BX);
        convgemm<1, false, false, true><<<gridC, 256>>>(out_w, pstr, plog, nullptr, out_b, CX, 2 * FX, SX);
    }
    nll_kernel<<<BX * SX, 256>>>(tgt);
    reduce_kernel<<<1, 1024>>>(out);
}

// round 8
// speedup vs baseline: 5.2093x; 1.9604x over previous
#include <cuda_runtime.h>
#include <math.h>
#include <stdint.h>

#define BXC 2
#define SXC 2048
#define FXC 512
#define IXC 1024
#define KXC 3
#define LXC 2
#define CXC 256

#define PI_F 3.14159265358979323846f

// ---------------- scratch (device globals; no allocation allowed) ------------
__device__ float g_a  [BXC*FXC*SXC];
__device__ float g_b  [BXC*FXC*SXC];
__device__ float g_h  [BXC*FXC*SXC];
__device__ float g_y1 [BXC*IXC*SXC];
__device__ float g_y2 [BXC*IXC*SXC];
__device__ float g_d  [BXC*FXC*SXC];
__device__ float g_sc [BXC*FXC*SXC];
__device__ float g_sh [BXC*FXC*SXC];
__device__ float g_str[BXC*2*FXC*SXC];
__device__ float g_log[BXC*CXC*SXC];
__device__ float g_fe [FXC];
__device__ float g_nll[BXC*SXC];

// ---------------- feature embedding ------------------------------------------
__global__ void fe_kernel() {
    int f = blockIdx.x * blockDim.x + threadIdx.x;
    if (f < FXC) {
        float ff = (float)f + 1.0f;
        float additive = fmodf(ff, 2.0f);
        float g = (ff - additive) * 0.5f;
        g = g * (8.0f / (float)FXC) - logf((float)CXC / (2.0f * PI_F));
        g_fe[f] = expf(g) + additive * PI_F;
    }
}

// ---------------- embedding gather (also builds h = b + fe) -------------------
__global__ void embed_kernel(const int* __restrict__ inp,
                             const float* __restrict__ emb) {
    size_t idx = (size_t)blockIdx.x * blockDim.x + threadIdx.x;
    if (idx >= (size_t)BXC * FXC * SXC) return;
    int s = (int)(idx % SXC);
    int f = (int)((idx / SXC) % FXC);
    int b = (int)(idx / ((size_t)SXC * FXC));
    int tok = inp[b * SXC + s];
    float av = emb[(size_t)tok * (2 * FXC) + f];
    float bv = emb[(size_t)tok * (2 * FXC) + FXC + f];
    g_a[idx] = av;
    g_b[idx] = bv;
    g_h[idx] = bv + g_fe[f];
    (void)s;
}

// ================= tf32 tensor-core conv-GEMM (cp.async pipelined) ============
// Y[b,m,n] = act( sum_t sum_k W[m,k,t] * X[b,k,n+t-(TAPS-1)] ) (+bias[m])
// Channel-chunked (32 per chunk); taps read shifted views of a halo'd X tile.
// Block tile 128(M) x NT(N), 8 warps (2M x 4N), warp 64 x NT/4.
// mma.sync.m16n8k8 tf32, fp32 accumulate. fp32 bits fed directly (truncate).

#define CP16(d, s)     asm volatile("cp.async.cg.shared.global [%0], [%1], 16;" :: "r"(d), "l"(s))
#define CP16Z(d, s, n) asm volatile("cp.async.cg.shared.global [%0], [%1], 16, %2;" :: "r"(d), "l"(s), "r"(n))
#define CPCOMMIT()     asm volatile("cp.async.commit_group;")
#define CPWAIT1()      asm volatile("cp.async.wait_group 1;")

__device__ __forceinline__ void mma_tf32(float* c, const uint32_t* a, const uint32_t* b) {
    asm volatile(
        "mma.sync.aligned.m16n8k8.row.col.f32.tf32.tf32.f32 "
        "{%0,%1,%2,%3}, {%4,%5,%6,%7}, {%8,%9}, {%0,%1,%2,%3};"
        : "+f"(c[0]), "+f"(c[1]), "+f"(c[2]), "+f"(c[3])
        : "r"(a[0]), "r"(a[1]), "r"(a[2]), "r"(a[3]), "r"(b[0]), "r"(b[1]));
}

template <int TAPS, int NJ, bool RELU, bool BIAS>
__global__ __launch_bounds__(256)
void mm2(const float* __restrict__ A,
         const float* __restrict__ X,
         float* __restrict__ Y,
         const float* __restrict__ bias,
         int M, int Kd, int N) {
    constexpr int ACOLS = 32 * TAPS;
    constexpr int APAD  = ACOLS + 4;
    constexpr int XOFF  = (TAPS == 1) ? 0 : 4;
    constexpr int NT    = NJ * 32;
    constexpr int XPAD  = NT + XOFF + 8;
    constexpr int ASZ   = 128 * APAD;
    constexpr int XSZ   = 32 * XPAD;

    extern __shared__ float smbuf[];
    float* As0 = smbuf;
    float* As1 = smbuf + ASZ;
    float* Xs0 = smbuf + 2 * ASZ;
    float* Xs1 = smbuf + 2 * ASZ + XSZ;

    const int Kp = Kd * TAPS;
    const int b  = blockIdx.z;
    const int m0 = blockIdx.y * 128;
    const int n0 = blockIdx.x * NT;
    const int tid  = threadIdx.x;
    const int lane = tid & 31;
    const int w    = tid >> 5;
    const int wM   = (w >> 2) * 64;
    const int wN   = (w & 3) * (NT / 4);
    const int g    = lane >> 2;
    const int tig  = lane & 3;

    // loader coords
    const int arow = tid >> 1;                  // 0..127
    const int av0  = (tid & 1) * (ACOLS / 8);   // starting float4 within row
    const float* agp = A + (size_t)(m0 + arow) * Kp + (size_t)av0 * 4;
    const int xrow = tid >> 3;                  // 0..31
    const int xv   = tid & 7;                   // 8 groups of NJ float4s
    const float* xgp = X + ((size_t)b * Kd + xrow) * N + n0 + xv * NJ * 4;

    float c[4][NJ][4];
#pragma unroll
    for (int i = 0; i < 4; i++)
#pragma unroll
        for (int j = 0; j < NJ; j++)
#pragma unroll
            for (int q = 0; q < 4; q++) c[i][j][q] = 0.0f;

    auto load_chunk = [&](int st, int k0) {
        float* Ab = st ? As1 : As0;
        float* Xb = st ? Xs1 : Xs0;
        uint32_t ad = (uint32_t)__cvta_generic_to_shared(Ab + arow * APAD + av0 * 4);
        const float* as = agp + (size_t)k0 * TAPS;
#pragma unroll
        for (int v = 0; v < ACOLS / 8; v++)
            CP16(ad + v * 16, as + v * 4);
        uint32_t xd = (uint32_t)__cvta_generic_to_shared(Xb + xrow * XPAD + XOFF + xv * NJ * 4);
        const float* xs = xgp + (size_t)k0 * N;
#pragma unroll
        for (int v = 0; v < NJ; v++)
            CP16(xd + v * 16, xs + v * 4);
        if (TAPS == 3) {
            if (tid < 32) {
                const float* hs = X + ((size_t)b * Kd + k0 + tid) * N + (n0 > 0 ? n0 - 4 : 0);
                uint32_t hd = (uint32_t)__cvta_generic_to_shared(Xb + tid * XPAD);
                int ss = (n0 > 0) ? 16 : 0;
                CP16Z(hd, hs, ss);
            }
        }
    };

    auto compute_chunk = [&](int st) {
        const float* Ab = st ? As1 : As0;
        const float* Xb = st ? Xs1 : Xs0;
#pragma unroll
        for (int t = 0; t < TAPS; t++) {
#pragma unroll
            for (int kk = 0; kk < 4; kk++) {
                int kb = kk * 8 + tig;
                uint32_t af[4][4];
#pragma unroll
                for (int i = 0; i < 4; i++) {
                    const float* p = Ab + (wM + i * 16 + g) * APAD + kb * TAPS + t;
                    af[i][0] = __float_as_uint(p[0]);
                    af[i][1] = __float_as_uint(p[8 * APAD]);
                    af[i][2] = __float_as_uint(p[4 * TAPS]);
                    af[i][3] = __float_as_uint(p[8 * APAD + 4 * TAPS]);
                }
                uint32_t bf[NJ][2];
                const float* q0 = Xb + kb * XPAD + XOFF + (t - (TAPS - 1)) + wN + g;
#pragma unroll
                for (int j = 0; j < NJ; j++) {
                    bf[j][0] = __float_as_uint(q0[j * 8]);
                    bf[j][1] = __float_as_uint(q0[4 * XPAD + j * 8]);
                }
#pragma unroll
                for (int i = 0; i < 4; i++)
#pragma unroll
                    for (int j = 0; j < NJ; j++)
                        mma_tf32(c[i][j], af[i], bf[j]);
            }
        }
    };

    const int NC = Kd / 32;
    load_chunk(0, 0);
    CPCOMMIT();
    for (int cc = 0; cc < NC; cc++) {
        if (cc + 1 < NC) load_chunk((cc + 1) & 1, (cc + 1) * 32);
        CPCOMMIT();
        CPWAIT1();
        __syncthreads();
        compute_chunk(cc & 1);
        __syncthreads();
    }

    // ---- epilogue ----
#pragma unroll
    for (int i = 0; i < 4; i++) {
        int m = m0 + wM + i * 16 + g;
        float bi0 = BIAS ? bias[m] : 0.0f;
        float bi1 = BIAS ? bias[m + 8] : 0.0f;
#pragma unroll
        for (int j = 0; j < NJ; j++) {
            int n = n0 + wN + j * 8 + 2 * tig;
            float2 v0 = make_float2(c[i][j][0] + bi0, c[i][j][1] + bi0);
            float2 v1 = make_float2(c[i][j][2] + bi1, c[i][j][3] + bi1);
            if (RELU) {
                v0.x = fmaxf(v0.x, 0.0f); v0.y = fmaxf(v0.y, 0.0f);
                v1.x = fmaxf(v1.x, 0.0f); v1.y = fmaxf(v1.y, 0.0f);
            }
            *(float2*)&Y[((size_t)b * M + m) * N + n]     = v0;
            *(float2*)&Y[((size_t)b * M + m + 8) * N + n] = v1;
        }
    }
}

// ---------------- combine: cumsum over F, norm, EMA update -------------------
__global__ void combine_kernel() {
    int bs = blockIdx.x;
    int b = bs >> 11;
    int s = bs & 2047;
    int f = threadIdx.x;
    size_t idx = ((size_t)b * FXC + f) * SXC + s;

    float dv  = g_d[idx];
    float scv = g_sc[idx];
    float shv = g_sh[idx];

    int lane = f & 31, wid = f >> 5;

    float v = dv;
#pragma unroll
    for (int o = 1; o < 32; o <<= 1) {
        float t2 = __shfl_up_sync(0xffffffffu, v, o);
        if (lane >= o) v += t2;
    }
    __shared__ float wtot[16], wpref[16], red[16];
    __shared__ float bc[2];
    if (lane == 31) wtot[wid] = v;
    __syncthreads();
    if (f < 16) {
        float w = wtot[f];
#pragma unroll
        for (int o = 1; o < 16; o <<= 1) {
            float t2 = __shfl_up_sync(0x0000ffffu, w, o);
            if (f >= o) w += t2;
        }
        wpref[f] = w;
    }
    __syncthreads();
    float cum = v + (wid ? wpref[wid - 1] : 0.0f);

    float val = cum * (1.0f / (float)(s + 1)) * scv + shv;

    float r = val;
#pragma unroll
    for (int o = 16; o > 0; o >>= 1) r += __shfl_xor_sync(0xffffffffu, r, o);
    if (lane == 0) red[wid] = r;
    __syncthreads();
    if (f == 0) {
        float t2 = 0.0f;
        for (int i = 0; i < 16; i++) t2 += red[i];
        bc[0] = t2 * (1.0f / (float)FXC);
    }
    __syncthreads();
    float vc = val - bc[0];

    float q = vc * vc;
#pragma unroll
    for (int o = 16; o > 0; o >>= 1) q += __shfl_xor_sync(0xffffffffu, q, o);
    __syncthreads();
    if (lane == 0) red[wid] = q;
    __syncthreads();
    if (f == 0) {
        float t2 = 0.0f;
        for (int i = 0; i < 16; i++) t2 += red[i];
        bc[1] = sqrtf(t2) * rsqrtf((float)FXC) + 1e-5f;
    }
    __syncthreads();

    const float INIT_SCALE = 0.7071067811865476f;
    const float BETA = 0.99f;
    float cell = vc / bc[1] * INIT_SCALE;
    float aold = g_a[idx];
    float cnew = BETA * aold + (1.0f - BETA) * cell;
    g_a[idx] = cnew;
    float newb = g_b[idx] + cnew;
    g_b[idx] = newb;
    g_h[idx] = newb + g_fe[f];
}

// ---------------- build streams = concat([a,b], ch) --------------------------
__global__ void streams_kernel() {
    size_t idx = (size_t)blockIdx.x * blockDim.x + threadIdx.x;
    if (idx >= (size_t)BXC * FXC * SXC) return;
    int s = (int)(idx % SXC);
    int f = (int)((idx / SXC) % FXC);
    int b = (int)(idx / ((size_t)SXC * FXC));
    g_str[((size_t)b * 2 * FXC + f) * SXC + s]       = g_a[idx];
    g_str[((size_t)b * 2 * FXC + FXC + f) * SXC + s] = g_b[idx];
}

// ---------------- per-position NLL -------------------------------------------
__global__ void nll_kernel(const int* __restrict__ tgt) {
    int bs = blockIdx.x;
    int b = bs >> 11;
    int s = bs & 2047;
    int c = threadIdx.x;
    float x = g_log[((size_t)b * CXC + c) * SXC + s];

    int lane = c & 31, wid = c >> 5;
    __shared__ float red[8];
    __shared__ float bc[2];
    __shared__ float tval;

    float m = x;
#pragma unroll
    for (int o = 16; o > 0; o >>= 1) m = fmaxf(m, __shfl_xor_sync(0xffffffffu, m, o));
    if (lane == 0) red[wid] = m;
    __syncthreads();
    if (c == 0) {
        float t2 = red[0];
        for (int i = 1; i < 8; i++) t2 = fmaxf(t2, red[i]);
        bc[0] = t2;
    }
    __syncthreads();
    float e = expf(x - bc[0]);
#pragma unroll
    for (int o = 16; o > 0; o >>= 1) e += __shfl_xor_sync(0xffffffffu, e, o);
    __syncthreads();
    if (lane == 0) red[wid] = e;
    int tv = tgt[b * SXC + s];
    if (c == tv) tval = x;
    __syncthreads();
    if (c == 0) {
        float t2 = 0.0f;
        for (int i = 0; i < 8; i++) t2 += red[i];
        float lse = bc[0] + logf(t2);
        g_nll[bs] = lse - tval;
    }
}

// ---------------- deterministic final mean -----------------------------------
__global__ void reduce_kernel(float* __restrict__ out) {
    __shared__ float sh[1024];
    int t = threadIdx.x;
    float s = 0.0f;
    for (int i = t; i < BXC * SXC; i += 1024) s += g_nll[i];
    sh[t] = s;
    __syncthreads();
    for (int o = 512; o > 0; o >>= 1) {
        if (t < o) sh[t] += sh[t + o];
        __syncthreads();
    }
    if (t == 0) out[0] = sh[0] / (float)(BXC * SXC);
}

// ---------------- host orchestration -----------------------------------------
extern "C" void kernel_launch(void* const* d_in, const int* in_sizes, int n_in,
                              void* d_out, int out_size) {
    const int*   inp   = (const int*)d_in[0];
    const int*   tgt   = (const int*)d_in[1];
    const float* emb   = (const float*)d_in[2];
    const float* w0s   = (const float*)d_in[3];
    const float* w1s   = (const float*)d_in[4];
    const float* w2s   = (const float*)d_in[5];
    const float* out_w = (const float*)d_in[6];
    const float* out_b = (const float*)d_in[7];
    float* out = (float*)d_out;

    float *pa, *pb, *ph, *py1, *py2, *pd, *psc, *psh, *pstr, *plog;
    cudaGetSymbolAddress((void**)&pa,  g_a);
    cudaGetSymbolAddress((void**)&pb,  g_b);
    cudaGetSymbolAddress((void**)&ph,  g_h);
    cudaGetSymbolAddress((void**)&py1, g_y1);
    cudaGetSymbolAddress((void**)&py2, g_y2);
    cudaGetSymbolAddress((void**)&pd,  g_d);
    cudaGetSymbolAddress((void**)&psc, g_sc);
    cudaGetSymbolAddress((void**)&psh, g_sh);
    cudaGetSymbolAddress((void**)&pstr, g_str);
    cudaGetSymbolAddress((void**)&plog, g_log);

    // dynamic smem sizes (bytes)
    const int SM_P1N8 = 2 * (128 * 36  + 32 * 264) * 4;  // TAPS=1, NT=256 -> 104448
    const int SM_P3N8 = 2 * (128 * 100 + 32 * 268) * 4;  // TAPS=3, NT=256 -> 171008
    const int SM_P1N4 = 2 * (128 * 36  + 32 * 136) * 4;  // TAPS=1, NT=128 ->  71680

    cudaFuncSetAttribute((const void*)mm2<1, 8, true,  false>,
                         cudaFuncAttributeMaxDynamicSharedMemorySize, SM_P1N8);
    cudaFuncSetAttribute((const void*)mm2<3, 8, true,  false>,
                         cudaFuncAttributeMaxDynamicSharedMemorySize, SM_P3N8);
    cudaFuncSetAttribute((const void*)mm2<1, 4, false, false>,
                         cudaFuncAttributeMaxDynamicSharedMemorySize, SM_P1N4);
    cudaFuncSetAttribute((const void*)mm2<1, 4, false, true>,
                         cudaFuncAttributeMaxDynamicSharedMemorySize, SM_P1N4);

    fe_kernel<<<1, 512>>>();
    {
        size_t n = (size_t)BXC * FXC * SXC;
        embed_kernel<<<(unsigned)((n + 255) / 256), 256>>>(inp, emb);
    }

    float* outs[3] = {pd, psc, psh};

    for (int l = 0; l < LXC; ++l) {
        for (int m = 0; m < 3; ++m) {
            const float* W0 = w0s + (size_t)(l * 3 + m) * IXC * FXC;
            const float* W1 = w1s + (size_t)(l * 3 + m) * IXC * IXC * KXC;
            const float* W2 = w2s + (size_t)(l * 3 + m) * FXC * IXC;

            dim3 grid0(SXC / 256, IXC / 128, BXC);   // 8 x 8 x 2
            dim3 grid1(SXC / 256, IXC / 128, BXC);   // 8 x 8 x 2
            dim3 grid2(SXC / 128, FXC / 128, BXC);   // 16 x 4 x 2
            // conv0: F->I pointwise, input = h = b + fe, relu
            mm2<1, 8, true, false><<<grid0, 256, SM_P1N8>>>(W0, ph, py1, nullptr, IXC, FXC, SXC);
            // conv1: I->I causal k=3, relu
            mm2<3, 8, true, false><<<grid1, 256, SM_P3N8>>>(W1, py1, py2, nullptr, IXC, IXC, SXC);
            // conv2: I->F pointwise
            mm2<1, 4, false, false><<<grid2, 256, SM_P1N4>>>(W2, py2, outs[m], nullptr, FXC, IXC, SXC);
        }
        combine_kernel<<<BXC * SXC, 512>>>();
    }

    {
        size_t n = (size_t)BXC * FXC * SXC;
        streams_kernel<<<(unsigned)((n + 255) / 256), 256>>>();
    }
    {
        dim3 gridC(SXC / 128, CXC / 128, BXC);       // 16 x 2 x 2
        mm2<1, 4, false, true><<<gridC, 256, SM_P1N4>>>(out_w, pstr, plog, out_b, CXC, 2 * FXC, SXC);
    }
    nll_kernel<<<BXC * SXC, 256>>>(tgt);
    reduce_kernel<<<1, 1024>>>(out);
}

// round 9
// speedup vs baseline: 8.1799x; 1.5703x over previous
#include <cuda_runtime.h>
#include <math.h>
#include <stdint.h>

#define BXC 2
#define SXC 2048
#define FXC 512
#define IXC 1024
#define KXC 3
#define LXC 2
#define CXC 256

#define PI_F 3.14159265358979323846f

// ---------------- scratch (device globals; no allocation allowed) ------------
__device__ float g_a  [BXC*FXC*SXC];
__device__ float g_b  [BXC*FXC*SXC];
__device__ float g_h  [BXC*FXC*SXC];
__device__ float g_y1 [BXC*IXC*SXC];
__device__ float g_y2 [BXC*IXC*SXC];
__device__ float g_d  [BXC*FXC*SXC];
__device__ float g_sc [BXC*FXC*SXC];
__device__ float g_sh [BXC*FXC*SXC];
__device__ float g_str[BXC*2*FXC*SXC];
__device__ float g_log[BXC*CXC*SXC];
__device__ float g_fe [FXC];
__device__ float g_nll[BXC*SXC];

// packed bf16x2 weights (k-pairs in one u32; lo = even k, hi = odd k)
__device__ uint32_t g_wp0[6 * IXC * (FXC/2)];          // conv0: [sl][m][kp]        (256/row)
__device__ uint32_t g_wp3[6 * IXC * 3 * (IXC/2)];      // conv1: [sl][m][t][kp]     (1536/row)
__device__ uint32_t g_wp2[6 * FXC * (IXC/2)];          // conv2: [sl][m][kp]        (512/row)
__device__ uint32_t g_wpL[CXC * IXC];                  // logits: [m][kp]           (512/row)

__device__ __forceinline__ uint32_t pk(float lo, float hi) {
    uint32_t r;
    asm("cvt.rn.bf16x2.f32 %0, %1, %2;" : "=r"(r) : "f"(hi), "f"(lo));
    return r;
}

// ---------------- weight pre-pack kernels ------------------------------------
// TAPS=1 tensors are row-major [.., Kd] with Kd even: pairs never straddle rows.
__global__ void pack1_kernel(const float* __restrict__ W, uint32_t* __restrict__ P, int total) {
    int i = blockIdx.x * blockDim.x + threadIdx.x;
    if (i < total) {
        float2 v = *(const float2*)&W[(size_t)2 * i];
        P[i] = pk(v.x, v.y);
    }
}

// conv1: W [6*1024][1024][3] -> P [6*1024][3][512]
__global__ void pack3_kernel(const float* __restrict__ W, uint32_t* __restrict__ P) {
    int i = blockIdx.x * blockDim.x + threadIdx.x;
    if (i >= 6 * IXC * 3 * (IXC/2)) return;
    int kp = i & 511;
    int t  = (i >> 9) % 3;
    int m6 = i / 1536;
    const float* src = W + (size_t)m6 * (IXC * 3) + (size_t)kp * 6 + t;
    P[i] = pk(src[0], src[3]);
}

// ---------------- feature embedding ------------------------------------------
__global__ void fe_kernel() {
    int f = blockIdx.x * blockDim.x + threadIdx.x;
    if (f < FXC) {
        float ff = (float)f + 1.0f;
        float additive = fmodf(ff, 2.0f);
        float g = (ff - additive) * 0.5f;
        g = g * (8.0f / (float)FXC) - logf((float)CXC / (2.0f * PI_F));
        g_fe[f] = expf(g) + additive * PI_F;
    }
}

// ---------------- embedding gather (also builds h = b + fe) -------------------
__global__ void embed_kernel(const int* __restrict__ inp,
                             const float* __restrict__ emb) {
    size_t idx = (size_t)blockIdx.x * blockDim.x + threadIdx.x;
    if (idx >= (size_t)BXC * FXC * SXC) return;
    int s = (int)(idx % SXC);
    int f = (int)((idx / SXC) % FXC);
    int b = (int)(idx / ((size_t)SXC * FXC));
    int tok = inp[b * SXC + s];
    float av = emb[(size_t)tok * (2 * FXC) + f];
    float bv = emb[(size_t)tok * (2 * FXC) + FXC + f];
    g_a[idx] = av;
    g_b[idx] = bv;
    g_h[idx] = bv + g_fe[f];
}

// ================= bf16 tensor-core conv-GEMM ================================
// Y[b,m,n] = act( sum_t sum_k W[m,k,t] * X[b,k,n+t-(TAPS-1)] ) (+bias[m])
// A: pre-packed bf16x2 in gmem, loaded via cp.async (double-buffered smem).
// X: fp32 in gmem, LDG -> cvt.bf16x2 (pair channels) -> STS (reg double buffer).
// Block tile 128(M) x 128(N), 8 warps (2M x 4N), warp 64x32.
// mma.sync.m16n8k16 bf16, fp32 accumulate.

#define CP16(d, s)  asm volatile("cp.async.cg.shared.global [%0], [%1], 16;" :: "r"(d), "l"(s))
#define CPCOMMIT()  asm volatile("cp.async.commit_group;")
#define CPWAIT0()   asm volatile("cp.async.wait_group 0;")

__device__ __forceinline__ void mma_bf16(float* c, const uint32_t* a, const uint32_t* b) {
    asm volatile(
        "mma.sync.aligned.m16n8k16.row.col.f32.bf16.bf16.f32 "
        "{%0,%1,%2,%3}, {%4,%5,%6,%7}, {%8,%9}, {%0,%1,%2,%3};"
        : "+f"(c[0]), "+f"(c[1]), "+f"(c[2]), "+f"(c[3])
        : "r"(a[0]), "r"(a[1]), "r"(a[2]), "r"(a[3]), "r"(b[0]), "r"(b[1]));
}

template <int TAPS, bool RELU, bool BIAS>
__global__ __launch_bounds__(256, 2)
void mmbf(const uint32_t* __restrict__ Ap,
          const float* __restrict__ X,
          float* __restrict__ Y,
          const float* __restrict__ bias,
          int M, int Kd, int N, int ApS) {
    constexpr int AC   = 16 * TAPS;      // u32 per row per chunk
    constexpr int AST  = AC + 4;         // smem row stride (u32): 52 / 20
    constexpr int XOFF = 4;
    constexpr int XST  = 136;            // smem row stride (u32), 136 % 32 == 8
    constexpr int ASZ  = 128 * AST;
    constexpr int XSZ  = 16 * XST;

    extern __shared__ uint32_t sm[];
    uint32_t* As0 = sm;
    uint32_t* As1 = sm + ASZ;
    uint32_t* Xs0 = sm + 2 * ASZ;
    uint32_t* Xs1 = sm + 2 * ASZ + XSZ;

    const int b  = blockIdx.z;
    const int m0 = blockIdx.y * 128;
    const int n0 = blockIdx.x * 128;
    const int tid  = threadIdx.x;
    const int lane = tid & 31;
    const int w    = tid >> 5;
    const int wM   = (w >> 2) * 64;
    const int wN   = (w & 3) * 32;
    const int g    = lane >> 2;
    const int tig  = lane & 3;

    // --- A loader coords (cp.async): thread -> (row m, half) ---
    const int am   = tid >> 1;
    const int ah   = tid & 1;
    const uint32_t* agp = Ap + (size_t)(m0 + am) * ApS + ah * 8;
    uint32_t asm0 = (uint32_t)__cvta_generic_to_shared(As0 + am * AST + ah * 8);
    uint32_t asm1 = (uint32_t)__cvta_generic_to_shared(As1 + am * AST + ah * 8);

    // --- X loader coords: 2 jobs of (kp, n-quad) ---
    const int kpa = tid >> 5;            // job0 kp 0..7
    const int nqa = tid & 31;
    const int kpb = kpa + 8;             // job1 kp 8..15
    const float* xga = X + ((size_t)b * Kd + 2 * kpa) * N + n0 + 4 * nqa;
    const float* xgb = X + ((size_t)b * Kd + 2 * kpb) * N + n0 + 4 * nqa;

    float c[4][4][4];
#pragma unroll
    for (int i = 0; i < 4; i++)
#pragma unroll
        for (int j = 0; j < 4; j++)
#pragma unroll
            for (int q = 0; q < 4; q++) c[i][j][q] = 0.0f;

    uint32_t xu[2][4];
    uint32_t xh[2];

    auto ldA = [&](int st, int ck) {
        const uint32_t* s0 = agp + (size_t)ck * 16;
        uint32_t d0 = (st ? asm1 : asm0);
#pragma unroll
        for (int t = 0; t < TAPS; t++) {
            CP16(d0 + t * 16 * 4, s0 + t * (Kd / 2));
            CP16(d0 + t * 16 * 4 + 16, s0 + t * (Kd / 2) + 4);
        }
    };

    auto ldX = [&](int ck) {
        const float* p0 = xga + (size_t)(ck * 32) * N;
        const float* p1 = xgb + (size_t)(ck * 32) * N;
        float4 r0 = *(const float4*)p0;
        float4 r1 = *(const float4*)(p0 + N);
        xu[0][0] = pk(r0.x, r1.x); xu[0][1] = pk(r0.y, r1.y);
        xu[0][2] = pk(r0.z, r1.z); xu[0][3] = pk(r0.w, r1.w);
        float4 r2 = *(const float4*)p1;
        float4 r3 = *(const float4*)(p1 + N);
        xu[1][0] = pk(r2.x, r3.x); xu[1][1] = pk(r2.y, r3.y);
        xu[1][2] = pk(r2.z, r3.z); xu[1][3] = pk(r2.w, r3.w);
        if (TAPS == 3) {
            if (tid < 16) {
                if (n0 > 0) {
                    const float* h0 = X + ((size_t)b * Kd + ck * 32 + 2 * tid) * N + n0 - 2;
                    const float* h1 = h0 + N;
                    xh[0] = pk(h0[0], h1[0]);
                    xh[1] = pk(h0[1], h1[1]);
                } else {
                    xh[0] = 0u; xh[1] = 0u;
                }
            }
        }
    };

    auto stX = [&](int st) {
        uint32_t* Xb = st ? Xs1 : Xs0;
        *(uint4*)&Xb[kpa * XST + XOFF + 4 * nqa] = make_uint4(xu[0][0], xu[0][1], xu[0][2], xu[0][3]);
        *(uint4*)&Xb[kpb * XST + XOFF + 4 * nqa] = make_uint4(xu[1][0], xu[1][1], xu[1][2], xu[1][3]);
        if (TAPS == 3) {
            if (tid < 16) {
                Xb[tid * XST + 2] = xh[0];
                Xb[tid * XST + 3] = xh[1];
            }
        }
    };

    auto compute = [&](int st) {
        const uint32_t* Ab = st ? As1 : As0;
        const uint32_t* Xb = st ? Xs1 : Xs0;
#pragma unroll
        for (int t = 0; t < TAPS; t++) {
#pragma unroll
            for (int s = 0; s < 2; s++) {
                uint32_t af[4][4];
#pragma unroll
                for (int i = 0; i < 4; i++) {
                    const uint32_t* p = Ab + (wM + i * 16 + g) * AST + t * 16 + s * 8 + tig;
                    af[i][0] = p[0];
                    af[i][1] = p[8 * AST];
                    af[i][2] = p[4];
                    af[i][3] = p[8 * AST + 4];
                }
                uint32_t bf[4][2];
                const uint32_t* q0 = Xb + (s * 8 + tig) * XST + XOFF + (t - (TAPS - 1)) + wN + g;
#pragma unroll
                for (int j = 0; j < 4; j++) {
                    bf[j][0] = q0[j * 8];
                    bf[j][1] = q0[4 * XST + j * 8];
                }
#pragma unroll
                for (int i = 0; i < 4; i++)
#pragma unroll
                    for (int j = 0; j < 4; j++)
                        mma_bf16(c[i][j], af[i], bf[j]);
            }
        }
    };

    const int NC = Kd / 32;
    // preload chunk 0
    ldA(0, 0); CPCOMMIT();
    ldX(0); stX(0);
    CPWAIT0();
    __syncthreads();

    for (int cc = 0; cc < NC; cc++) {
        int nx = cc + 1;
        if (nx < NC) {
            ldA(nx & 1, nx); CPCOMMIT();
            ldX(nx);
        }
        compute(cc & 1);
        __syncthreads();
        if (nx < NC) {
            stX(nx & 1);
            CPWAIT0();
            __syncthreads();
        }
    }

    // ---- epilogue ----
#pragma unroll
    for (int i = 0; i < 4; i++) {
        int m = m0 + wM + i * 16 + g;
        float bi0 = BIAS ? bias[m] : 0.0f;
        float bi1 = BIAS ? bias[m + 8] : 0.0f;
#pragma unroll
        for (int j = 0; j < 4; j++) {
            int n = n0 + wN + j * 8 + 2 * tig;
            float2 v0 = make_float2(c[i][j][0] + bi0, c[i][j][1] + bi0);
            float2 v1 = make_float2(c[i][j][2] + bi1, c[i][j][3] + bi1);
            if (RELU) {
                v0.x = fmaxf(v0.x, 0.0f); v0.y = fmaxf(v0.y, 0.0f);
                v1.x = fmaxf(v1.x, 0.0f); v1.y = fmaxf(v1.y, 0.0f);
            }
            *(float2*)&Y[((size_t)b * M + m) * N + n]     = v0;
            *(float2*)&Y[((size_t)b * M + m + 8) * N + n] = v1;
        }
    }
}

// ---------------- combine: cumsum over F, norm, EMA update -------------------
__global__ void combine_kernel() {
    int bs = blockIdx.x;
    int b = bs >> 11;
    int s = bs & 2047;
    int f = threadIdx.x;
    size_t idx = ((size_t)b * FXC + f) * SXC + s;

    float dv  = g_d[idx];
    float scv = g_sc[idx];
    float shv = g_sh[idx];

    int lane = f & 31, wid = f >> 5;

    float v = dv;
#pragma unroll
    for (int o = 1; o < 32; o <<= 1) {
        float t2 = __shfl_up_sync(0xffffffffu, v, o);
        if (lane >= o) v += t2;
    }
    __shared__ float wtot[16], wpref[16], red[16];
    __shared__ float bc[2];
    if (lane == 31) wtot[wid] = v;
    __syncthreads();
    if (f < 16) {
        float w = wtot[f];
#pragma unroll
        for (int o = 1; o < 16; o <<= 1) {
            float t2 = __shfl_up_sync(0x0000ffffu, w, o);
            if (f >= o) w += t2;
        }
        wpref[f] = w;
    }
    __syncthreads();
    float cum = v + (wid ? wpref[wid - 1] : 0.0f);

    float val = cum * (1.0f / (float)(s + 1)) * scv + shv;

    float r = val;
#pragma unroll
    for (int o = 16; o > 0; o >>= 1) r += __shfl_xor_sync(0xffffffffu, r, o);
    if (lane == 0) red[wid] = r;
    __syncthreads();
    if (f == 0) {
        float t2 = 0.0f;
        for (int i = 0; i < 16; i++) t2 += red[i];
        bc[0] = t2 * (1.0f / (float)FXC);
    }
    __syncthreads();
    float vc = val - bc[0];

    float q = vc * vc;
#pragma unroll
    for (int o = 16; o > 0; o >>= 1) q += __shfl_xor_sync(0xffffffffu, q, o);
    __syncthreads();
    if (lane == 0) red[wid] = q;
    __syncthreads();
    if (f == 0) {
        float t2 = 0.0f;
        for (int i = 0; i < 16; i++) t2 += red[i];
        bc[1] = sqrtf(t2) * rsqrtf((float)FXC) + 1e-5f;
    }
    __syncthreads();

    const float INIT_SCALE = 0.7071067811865476f;
    const float BETA = 0.99f;
    float cell = vc / bc[1] * INIT_SCALE;
    float aold = g_a[idx];
    float cnew = BETA * aold + (1.0f - BETA) * cell;
    g_a[idx] = cnew;
    float newb = g_b[idx] + cnew;
    g_b[idx] = newb;
    g_h[idx] = newb + g_fe[f];
}

// ---------------- build streams = concat([a,b], ch) --------------------------
__global__ void streams_kernel() {
    size_t idx = (size_t)blockIdx.x * blockDim.x + threadIdx.x;
    if (idx >= (size_t)BXC * FXC * SXC) return;
    int s = (int)(idx % SXC);
    int f = (int)((idx / SXC) % FXC);
    int b = (int)(idx / ((size_t)SXC * FXC));
    g_str[((size_t)b * 2 * FXC + f) * SXC + s]       = g_a[idx];
    g_str[((size_t)b * 2 * FXC + FXC + f) * SXC + s] = g_b[idx];
}

// ---------------- per-position NLL -------------------------------------------
__global__ void nll_kernel(const int* __restrict__ tgt) {
    int bs = blockIdx.x;
    int b = bs >> 11;
    int s = bs & 2047;
    int c = threadIdx.x;
    float x = g_log[((size_t)b * CXC + c) * SXC + s];

    int lane = c & 31, wid = c >> 5;
    __shared__ float red[8];
    __shared__ float bc[2];
    __shared__ float tval;

    float m = x;
#pragma unroll
    for (int o = 16; o > 0; o >>= 1) m = fmaxf(m, __shfl_xor_sync(0xffffffffu, m, o));
    if (lane == 0) red[wid] = m;
    __syncthreads();
    if (c == 0) {
        float t2 = red[0];
        for (int i = 1; i < 8; i++) t2 = fmaxf(t2, red[i]);
        bc[0] = t2;
    }
    __syncthreads();
    float e = expf(x - bc[0]);
#pragma unroll
    for (int o = 16; o > 0; o >>= 1) e += __shfl_xor_sync(0xffffffffu, e, o);
    __syncthreads();
    if (lane == 0) red[wid] = e;
    int tv = tgt[b * SXC + s];
    if (c == tv) tval = x;
    __syncthreads();
    if (c == 0) {
        float t2 = 0.0f;
        for (int i = 0; i < 8; i++) t2 += red[i];
        float lse = bc[0] + logf(t2);
        g_nll[bs] = lse - tval;
    }
}

// ---------------- deterministic final mean -----------------------------------
__global__ void reduce_kernel(float* __restrict__ out) {
    __shared__ float sh[1024];
    int t = threadIdx.x;
    float s = 0.0f;
    for (int i = t; i < BXC * SXC; i += 1024) s += g_nll[i];
    sh[t] = s;
    __syncthreads();
    for (int o = 512; o > 0; o >>= 1) {
        if (t < o) sh[t] += sh[t + o];
        __syncthreads();
    }
    if (t == 0) out[0] = sh[0] / (float)(BXC * SXC);
}

// ---------------- host orchestration -----------------------------------------
extern "C" void kernel_launch(void* const* d_in, const int* in_sizes, int n_in,
                              void* d_out, int out_size) {
    const int*   inp   = (const int*)d_in[0];
    const int*   tgt   = (const int*)d_in[1];
    const float* emb   = (const float*)d_in[2];
    const float* w0s   = (const float*)d_in[3];
    const float* w1s   = (const float*)d_in[4];
    const float* w2s   = (const float*)d_in[5];
    const float* out_w = (const float*)d_in[6];
    const float* out_b = (const float*)d_in[7];
    float* out = (float*)d_out;

    float *pa, *pb, *ph, *py1, *py2, *pd, *psc, *psh, *pstr, *plog;
    uint32_t *pw0, *pw3, *pw2, *pwL;
    cudaGetSymbolAddress((void**)&pa,  g_a);
    cudaGetSymbolAddress((void**)&pb,  g_b);
    cudaGetSymbolAddress((void**)&ph,  g_h);
    cudaGetSymbolAddress((void**)&py1, g_y1);
    cudaGetSymbolAddress((void**)&py2, g_y2);
    cudaGetSymbolAddress((void**)&pd,  g_d);
    cudaGetSymbolAddress((void**)&psc, g_sc);
    cudaGetSymbolAddress((void**)&psh, g_sh);
    cudaGetSymbolAddress((void**)&pstr, g_str);
    cudaGetSymbolAddress((void**)&plog, g_log);
    cudaGetSymbolAddress((void**)&pw0, g_wp0);
    cudaGetSymbolAddress((void**)&pw3, g_wp3);
    cudaGetSymbolAddress((void**)&pw2, g_wp2);
    cudaGetSymbolAddress((void**)&pwL, g_wpL);

    // dynamic smem sizes (bytes)
    const int SM_T3 = (2 * (128 * 52) + 2 * (16 * 136)) * 4;   // 70656
    const int SM_T1 = (2 * (128 * 20) + 2 * (16 * 136)) * 4;   // 37888

    cudaFuncSetAttribute((const void*)mmbf<1, true,  false>,
                         cudaFuncAttributeMaxDynamicSharedMemorySize, SM_T1);
    cudaFuncSetAttribute((const void*)mmbf<3, true,  false>,
                         cudaFuncAttributeMaxDynamicSharedMemorySize, SM_T3);
    cudaFuncSetAttribute((const void*)mmbf<1, false, false>,
                         cudaFuncAttributeMaxDynamicSharedMemorySize, SM_T1);
    cudaFuncSetAttribute((const void*)mmbf<1, false, true>,
                         cudaFuncAttributeMaxDynamicSharedMemorySize, SM_T1);

    // ---- weight pre-pack ----
    {
        int t0 = 6 * IXC * (FXC/2);
        pack1_kernel<<<(t0 + 255) / 256, 256>>>(w0s, pw0, t0);
        int t3 = 6 * IXC * 3 * (IXC/2);
        pack3_kernel<<<(t3 + 255) / 256, 256>>>(w1s, pw3);
        int t2 = 6 * FXC * (IXC/2);
        pack1_kernel<<<(t2 + 255) / 256, 256>>>(w2s, pw2, t2);
        int tL = CXC * IXC;
        pack1_kernel<<<(tL + 255) / 256, 256>>>(out_w, pwL, tL);
    }

    fe_kernel<<<1, 512>>>();
    {
        size_t n = (size_t)BXC * FXC * SXC;
        embed_kernel<<<(unsigned)((n + 255) / 256), 256>>>(inp, emb);
    }

    float* outs[3] = {pd, psc, psh};

    for (int l = 0; l < LXC; ++l) {
        for (int m = 0; m < 3; ++m) {
            int sl = l * 3 + m;
            const uint32_t* W0 = pw0 + (size_t)sl * IXC * (FXC/2);
            const uint32_t* W3 = pw3 + (size_t)sl * IXC * 3 * (IXC/2);
            const uint32_t* W2 = pw2 + (size_t)sl * FXC * (IXC/2);

            dim3 grid0(SXC / 128, IXC / 128, BXC);   // 16 x 8 x 2
            dim3 grid1(SXC / 128, IXC / 128, BXC);   // 16 x 8 x 2
            dim3 grid2(SXC / 128, FXC / 128, BXC);   // 16 x 4 x 2
            // conv0: F->I pointwise, input = h = b + fe, relu
            mmbf<1, true, false><<<grid0, 256, SM_T1>>>(W0, ph, py1, nullptr, IXC, FXC, SXC, FXC/2);
            // conv1: I->I causal k=3, relu
            mmbf<3, true, false><<<grid1, 256, SM_T3>>>(W3, py1, py2, nullptr, IXC, IXC, SXC, 3*(IXC/2));
            // conv2: I->F pointwise
            mmbf<1, false, false><<<grid2, 256, SM_T1>>>(W2, py2, outs[m], nullptr, FXC, IXC, SXC, IXC/2);
        }
        combine_kernel<<<BXC * SXC, 512>>>();
    }

    {
        size_t n = (size_t)BXC * FXC * SXC;
        streams_kernel<<<(unsigned)((n + 255) / 256), 256>>>();
    }
    {
        dim3 gridC(SXC / 128, CXC / 128, BXC);       // 16 x 2 x 2
        mmbf<1, false, true><<<gridC, 256, SM_T1>>>(pwL, pstr, plog, out_b, CXC, 2 * FXC, SXC, IXC);
    }
    nll_kernel<<<BXC * SXC, 256>>>(tgt);
    reduce_kernel<<<1, 1024>>>(out);
}

// round 13
// speedup vs baseline: 8.5325x; 1.0431x over previous
#include <cuda_runtime.h>
#include <math.h>
#include <stdint.h>

#define BXC 2
#define SXC 2048
#define FXC 512
#define IXC 1024
#define KXC 3
#define LXC 2
#define CXC 256

#define PI_F 3.14159265358979323846f

// ---------------- scratch (device globals; no allocation allowed) ------------
__device__ float g_a  [BXC*FXC*SXC];
__device__ float g_b  [BXC*FXC*SXC];
__device__ float g_h  [BXC*FXC*SXC];
__device__ float g_y1 [BXC*IXC*SXC];
__device__ float g_y2 [BXC*IXC*SXC];
__device__ float g_d  [BXC*FXC*SXC];
__device__ float g_sc [BXC*FXC*SXC];
__device__ float g_sh [BXC*FXC*SXC];
__device__ float g_str[BXC*2*FXC*SXC];
__device__ float g_log[BXC*CXC*SXC];
__device__ float g_fe [FXC];
__device__ float g_nll[BXC*SXC];

// packed bf16x2 weights (k-pairs in one u32; lo = even k, hi = odd k)
__device__ uint32_t g_wp0[6 * IXC * (FXC/2)];          // conv0: [sl][m][kp]        (256/row)
__device__ uint32_t g_wp3[6 * IXC * 3 * (IXC/2)];      // conv1: [sl][m][t][kp]     (1536/row)
__device__ uint32_t g_wp2[6 * FXC * (IXC/2)];          // conv2: [sl][m][kp]        (512/row)
__device__ uint32_t g_wpL[CXC * IXC];                  // logits: [m][kp]           (512/row)

__device__ __forceinline__ uint32_t pk(float lo, float hi) {
    uint32_t r;
    asm("cvt.rn.bf16x2.f32 %0, %1, %2;" : "=r"(r) : "f"(hi), "f"(lo));
    return r;
}

// ---------------- weight pre-pack kernels ------------------------------------
__global__ void pack1_kernel(const float* __restrict__ W, uint32_t* __restrict__ P, int total) {
    int i = blockIdx.x * blockDim.x + threadIdx.x;
    if (i < total) {
        float2 v = *(const float2*)&W[(size_t)2 * i];
        P[i] = pk(v.x, v.y);
    }
}

// conv1: W [6*1024][1024][3] -> P [6*1024][3][512]
__global__ void pack3_kernel(const float* __restrict__ W, uint32_t* __restrict__ P) {
    int i = blockIdx.x * blockDim.x + threadIdx.x;
    if (i >= 6 * IXC * 3 * (IXC/2)) return;
    int kp = i & 511;
    int t  = (i >> 9) % 3;
    int m6 = i / 1536;
    const float* src = W + (size_t)m6 * (IXC * 3) + (size_t)kp * 6 + t;
    P[i] = pk(src[0], src[3]);
}

// ---------------- feature embedding ------------------------------------------
__global__ void fe_kernel() {
    int f = blockIdx.x * blockDim.x + threadIdx.x;
    if (f < FXC) {
        float ff = (float)f + 1.0f;
        float additive = fmodf(ff, 2.0f);
        float g = (ff - additive) * 0.5f;
        g = g * (8.0f / (float)FXC) - logf((float)CXC / (2.0f * PI_F));
        g_fe[f] = expf(g) + additive * PI_F;
    }
}

// ---------------- embedding gather (also builds h = b + fe) -------------------
__global__ void embed_kernel(const int* __restrict__ inp,
                             const float* __restrict__ emb) {
    size_t idx = (size_t)blockIdx.x * blockDim.x + threadIdx.x;
    if (idx >= (size_t)BXC * FXC * SXC) return;
    int s = (int)(idx % SXC);
    int f = (int)((idx / SXC) % FXC);
    int b = (int)(idx / ((size_t)SXC * FXC));
    int tok = inp[b * SXC + s];
    float av = emb[(size_t)tok * (2 * FXC) + f];
    float bv = emb[(size_t)tok * (2 * FXC) + FXC + f];
    g_a[idx] = av;
    g_b[idx] = bv;
    g_h[idx] = bv + g_fe[f];
}

// ================= bf16 tensor-core conv-GEMM ================================
#define CP16(d, s)  asm volatile("cp.async.cg.shared.global [%0], [%1], 16;" :: "r"(d), "l"(s))
#define CPCOMMIT()  asm volatile("cp.async.commit_group;")
#define CPWAIT0()   asm volatile("cp.async.wait_group 0;")

__device__ __forceinline__ void mma_bf16(float* c, const uint32_t* a, const uint32_t* b) {
    asm volatile(
        "mma.sync.aligned.m16n8k16.row.col.f32.bf16.bf16.f32 "
        "{%0,%1,%2,%3}, {%4,%5,%6,%7}, {%8,%9}, {%0,%1,%2,%3};"
        : "+f"(c[0]), "+f"(c[1]), "+f"(c[2]), "+f"(c[3])
        : "r"(a[0]), "r"(a[1]), "r"(a[2]), "r"(a[3]), "r"(b[0]), "r"(b[1]));
}

template <int TAPS, bool RELU, bool BIAS>
__global__ __launch_bounds__(256, 2)
void mmbf(const uint32_t* __restrict__ Ap,
          const float* __restrict__ X,
          float* __restrict__ Y,
          const float* __restrict__ bias,
          int M, int Kd, int N, int ApS) {
    constexpr int AC   = 16 * TAPS;
    constexpr int AST  = AC + 4;
    constexpr int XOFF = 4;
    constexpr int XST  = 136;
    constexpr int ASZ  = 128 * AST;
    constexpr int XSZ  = 16 * XST;

    extern __shared__ uint32_t sm[];
    uint32_t* As0 = sm;
    uint32_t* As1 = sm + ASZ;
    uint32_t* Xs0 = sm + 2 * ASZ;
    uint32_t* Xs1 = sm + 2 * ASZ + XSZ;

    const int b  = blockIdx.z;
    const int m0 = blockIdx.y * 128;
    const int n0 = blockIdx.x * 128;
    const int tid  = threadIdx.x;
    const int lane = tid & 31;
    const int w    = tid >> 5;
    const int wM   = (w >> 2) * 64;
    const int wN   = (w & 3) * 32;
    const int g    = lane >> 2;
    const int tig  = lane & 3;

    const int am   = tid >> 1;
    const int ah   = tid & 1;
    const uint32_t* agp = Ap + (size_t)(m0 + am) * ApS + ah * 8;
    uint32_t asm0 = (uint32_t)__cvta_generic_to_shared(As0 + am * AST + ah * 8);
    uint32_t asm1 = (uint32_t)__cvta_generic_to_shared(As1 + am * AST + ah * 8);

    const int kpa = tid >> 5;
    const int nqa = tid & 31;
    const int kpb = kpa + 8;
    const float* xga = X + ((size_t)b * Kd + 2 * kpa) * N + n0 + 4 * nqa;
    const float* xgb = X + ((size_t)b * Kd + 2 * kpb) * N + n0 + 4 * nqa;

    float c[4][4][4];
#pragma unroll
    for (int i = 0; i < 4; i++)
#pragma unroll
        for (int j = 0; j < 4; j++)
#pragma unroll
            for (int q = 0; q < 4; q++) c[i][j][q] = 0.0f;

    uint32_t xu[2][4];
    uint32_t xh[2];

    auto ldA = [&](int st, int ck) {
        const uint32_t* s0 = agp + (size_t)ck * 16;
        uint32_t d0 = (st ? asm1 : asm0);
#pragma unroll
        for (int t = 0; t < TAPS; t++) {
            CP16(d0 + t * 16 * 4, s0 + t * (Kd / 2));
            CP16(d0 + t * 16 * 4 + 16, s0 + t * (Kd / 2) + 4);
        }
    };

    auto ldX = [&](int ck) {
        const float* p0 = xga + (size_t)(ck * 32) * N;
        const float* p1 = xgb + (size_t)(ck * 32) * N;
        float4 r0 = *(const float4*)p0;
        float4 r1 = *(const float4*)(p0 + N);
        xu[0][0] = pk(r0.x, r1.x); xu[0][1] = pk(r0.y, r1.y);
        xu[0][2] = pk(r0.z, r1.z); xu[0][3] = pk(r0.w, r1.w);
        float4 r2 = *(const float4*)p1;
        float4 r3 = *(const float4*)(p1 + N);
        xu[1][0] = pk(r2.x, r3.x); xu[1][1] = pk(r2.y, r3.y);
        xu[1][2] = pk(r2.z, r3.z); xu[1][3] = pk(r2.w, r3.w);
        if (TAPS == 3) {
            if (tid < 16) {
                if (n0 > 0) {
                    const float* h0 = X + ((size_t)b * Kd + ck * 32 + 2 * tid) * N + n0 - 2;
                    const float* h1 = h0 + N;
                    xh[0] = pk(h0[0], h1[0]);
                    xh[1] = pk(h0[1], h1[1]);
                } else {
                    xh[0] = 0u; xh[1] = 0u;
                }
            }
        }
    };

    auto stX = [&](int st) {
        uint32_t* Xb = st ? Xs1 : Xs0;
        *(uint4*)&Xb[kpa * XST + XOFF + 4 * nqa] = make_uint4(xu[0][0], xu[0][1], xu[0][2], xu[0][3]);
        *(uint4*)&Xb[kpb * XST + XOFF + 4 * nqa] = make_uint4(xu[1][0], xu[1][1], xu[1][2], xu[1][3]);
        if (TAPS == 3) {
            if (tid < 16) {
                Xb[tid * XST + 2] = xh[0];
                Xb[tid * XST + 3] = xh[1];
            }
        }
    };

    auto compute = [&](int st) {
        const uint32_t* Ab = st ? As1 : As0;
        const uint32_t* Xb = st ? Xs1 : Xs0;
#pragma unroll
        for (int t = 0; t < TAPS; t++) {
#pragma unroll
            for (int s = 0; s < 2; s++) {
                uint32_t af[4][4];
#pragma unroll
                for (int i = 0; i < 4; i++) {
                    const uint32_t* p = Ab + (wM + i * 16 + g) * AST + t * 16 + s * 8 + tig;
                    af[i][0] = p[0];
                    af[i][1] = p[8 * AST];
                    af[i][2] = p[4];
                    af[i][3] = p[8 * AST + 4];
                }
                uint32_t bf[4][2];
                const uint32_t* q0 = Xb + (s * 8 + tig) * XST + XOFF + (t - (TAPS - 1)) + wN + g;
#pragma unroll
                for (int j = 0; j < 4; j++) {
                    bf[j][0] = q0[j * 8];
                    bf[j][1] = q0[4 * XST + j * 8];
                }
#pragma unroll
                for (int i = 0; i < 4; i++)
#pragma unroll
                    for (int j = 0; j < 4; j++)
                        mma_bf16(c[i][j], af[i], bf[j]);
            }
        }
    };

    const int NC = Kd / 32;
    ldA(0, 0); CPCOMMIT();
    ldX(0); stX(0);
    CPWAIT0();
    __syncthreads();

    for (int cc = 0; cc < NC; cc++) {
        int nx = cc + 1;
        if (nx < NC) {
            ldA(nx & 1, nx); CPCOMMIT();
            ldX(nx);
        }
        compute(cc & 1);
        __syncthreads();
        if (nx < NC) {
            stX(nx & 1);
            CPWAIT0();
            __syncthreads();
        }
    }

#pragma unroll
    for (int i = 0; i < 4; i++) {
        int m = m0 + wM + i * 16 + g;
        float bi0 = BIAS ? bias[m] : 0.0f;
        float bi1 = BIAS ? bias[m + 8] : 0.0f;
#pragma unroll
        for (int j = 0; j < 4; j++) {
            int n = n0 + wN + j * 8 + 2 * tig;
            float2 v0 = make_float2(c[i][j][0] + bi0, c[i][j][1] + bi0);
            float2 v1 = make_float2(c[i][j][2] + bi1, c[i][j][3] + bi1);
            if (RELU) {
                v0.x = fmaxf(v0.x, 0.0f); v0.y = fmaxf(v0.y, 0.0f);
                v1.x = fmaxf(v1.x, 0.0f); v1.y = fmaxf(v1.y, 0.0f);
            }
            *(float2*)&Y[((size_t)b * M + m) * N + n]     = v0;
            *(float2*)&Y[((size_t)b * M + m + 8) * N + n] = v1;
        }
    }
}

// ========== combine v2: coalesced two-pass, thread-per-s-column ==============
// Block: 256 threads = 4 f-partitions x 64 s-columns. Grid: (S/64, B).
// Partition p owns f in [p*128, (p+1)*128). All global accesses coalesced.
// Pass 1: per-partition local cumsum + algebraic stats
//   u[f] = cum_local*inv*sc + sh;  val[f] = u[f] + off_p*inv*sc
//   S1 = sum(Su_p + c_p*Ssc_p), S2 = sum(Suu_p + 2c_p*Susc_p + c_p^2*Sscsc_p)
// Pass 2: recompute with offsets, apply norm + EMA, write a/b/h (+streams).
template <bool LAST>
__global__ __launch_bounds__(256)
void combine2() {
    __shared__ float sTd[4][64], sSu[4][64], sSuu[4][64];
    __shared__ float sSusc[4][64], sSsc[4][64], sSscsc[4][64];
    __shared__ float sOff[4][64], sMean[64], sInvd[64];

    const int scol = threadIdx.x & 63;
    const int part = threadIdx.x >> 6;
    const int b = blockIdx.y;
    const int s = blockIdx.x * 64 + scol;
    const float inv = 1.0f / (float)(s + 1);
    const size_t base = (size_t)b * FXC * SXC + s;
    const int f0 = part * 128;

    float cum = 0.0f, Su = 0.0f, Suu = 0.0f, Susc = 0.0f, Ssc = 0.0f, Sscsc = 0.0f;
#pragma unroll 4
    for (int j = 0; j < 128; j++) {
        size_t id = base + (size_t)(f0 + j) * SXC;
        float dv = g_d[id];
        float sc = g_sc[id];
        float sh = g_sh[id];
        cum += dv;
        float u = cum * inv * sc + sh;
        Su += u; Suu += u * u; Susc += u * sc;
        Ssc += sc; Sscsc += sc * sc;
    }
    sTd[part][scol] = cum;
    sSu[part][scol] = Su;     sSuu[part][scol] = Suu;
    sSusc[part][scol] = Susc; sSsc[part][scol] = Ssc;
    sSscsc[part][scol] = Sscsc;
    __syncthreads();

    if (part == 0) {
        float off = 0.0f, S1 = 0.0f, S2 = 0.0f;
#pragma unroll
        for (int p = 0; p < 4; p++) {
            sOff[p][scol] = off;
            float cp = off * inv;
            S1 += sSu[p][scol] + cp * sSsc[p][scol];
            S2 += sSuu[p][scol] + 2.0f * cp * sSusc[p][scol] + cp * cp * sSscsc[p][scol];
            off += sTd[p][scol];
        }
        float mean = S1 * (1.0f / (float)FXC);
        float ssq = fmaxf(S2 - S1 * mean, 0.0f);
        float denom = sqrtf(ssq) * rsqrtf((float)FXC) + 1e-5f;
        sMean[scol] = mean;
        sInvd[scol] = 1.0f / denom;
    }
    __syncthreads();

    const float INIT_SCALE = 0.7071067811865476f;
    const float BETA = 0.99f;
    float off  = sOff[part][scol];
    float mean = sMean[scol];
    float invd = sInvd[scol];
    float cum2 = off;
#pragma unroll 4
    for (int j = 0; j < 128; j++) {
        int f = f0 + j;
        size_t id = base + (size_t)f * SXC;
        float dv = g_d[id];
        float sc = g_sc[id];
        float sh = g_sh[id];
        cum2 += dv;
        float val = cum2 * inv * sc + sh;
        float cell = (val - mean) * invd * INIT_SCALE;
        float cnew = BETA * g_a[id] + (1.0f - BETA) * cell;
        g_a[id] = cnew;
        float nb = g_b[id] + cnew;
        g_b[id] = nb;
        if (LAST) {
            size_t sb = ((size_t)b * 2 * FXC + f) * SXC + s;
            g_str[sb] = cnew;
            g_str[sb + (size_t)FXC * SXC] = nb;
        } else {
            g_h[id] = nb + g_fe[f];
        }
    }
}

// ---------------- per-position NLL -------------------------------------------
__global__ void nll_kernel(const int* __restrict__ tgt) {
    int bs = blockIdx.x;
    int b = bs >> 11;
    int s = bs & 2047;
    int c = threadIdx.x;
    float x = g_log[((size_t)b * CXC + c) * SXC + s];

    int lane = c & 31, wid = c >> 5;
    __shared__ float red[8];
    __shared__ float bc[2];
    __shared__ float tval;

    float m = x;
#pragma unroll
    for (int o = 16; o > 0; o >>= 1) m = fmaxf(m, __shfl_xor_sync(0xffffffffu, m, o));
    if (lane == 0) red[wid] = m;
    __syncthreads();
    if (c == 0) {
        float t2 = red[0];
        for (int i = 1; i < 8; i++) t2 = fmaxf(t2, red[i]);
        bc[0] = t2;
    }
    __syncthreads();
    float e = expf(x - bc[0]);
#pragma unroll
    for (int o = 16; o > 0; o >>= 1) e += __shfl_xor_sync(0xffffffffu, e, o);
    __syncthreads();
    if (lane == 0) red[wid] = e;
    int tv = tgt[b * SXC + s];
    if (c == tv) tval = x;
    __syncthreads();
    if (c == 0) {
        float t2 = 0.0f;
        for (int i = 0; i < 8; i++) t2 += red[i];
        float lse = bc[0] + logf(t2);
        g_nll[bs] = lse - tval;
    }
}

// ---------------- deterministic final mean -----------------------------------
__global__ void reduce_kernel(float* __restrict__ out) {
    __shared__ float sh[1024];
    int t = threadIdx.x;
    float s = 0.0f;
    for (int i = t; i < BXC * SXC; i += 1024) s += g_nll[i];
    sh[t] = s;
    __syncthreads();
    for (int o = 512; o > 0; o >>= 1) {
        if (t < o) sh[t] += sh[t + o];
        __syncthreads();
    }
    if (t == 0) out[0] = sh[0] / (float)(BXC * SXC);
}

// ---------------- host orchestration -----------------------------------------
extern "C" void kernel_launch(void* const* d_in, const int* in_sizes, int n_in,
                              void* d_out, int out_size) {
    const int*   inp   = (const int*)d_in[0];
    const int*   tgt   = (const int*)d_in[1];
    const float* emb   = (const float*)d_in[2];
    const float* w0s   = (const float*)d_in[3];
    const float* w1s   = (const float*)d_in[4];
    const float* w2s   = (const float*)d_in[5];
    const float* out_w = (const float*)d_in[6];
    const float* out_b = (const float*)d_in[7];
    float* out = (float*)d_out;

    float *pa, *pb, *ph, *py1, *py2, *pd, *psc, *psh, *pstr, *plog;
    uint32_t *pw0, *pw3, *pw2, *pwL;
    cudaGetSymbolAddress((void**)&pa,  g_a);
    cudaGetSymbolAddress((void**)&pb,  g_b);
    cudaGetSymbolAddress((void**)&ph,  g_h);
    cudaGetSymbolAddress((void**)&py1, g_y1);
    cudaGetSymbolAddress((void**)&py2, g_y2);
    cudaGetSymbolAddress((void**)&pd,  g_d);
    cudaGetSymbolAddress((void**)&psc, g_sc);
    cudaGetSymbolAddress((void**)&psh, g_sh);
    cudaGetSymbolAddress((void**)&pstr, g_str);
    cudaGetSymbolAddress((void**)&plog, g_log);
    cudaGetSymbolAddress((void**)&pw0, g_wp0);
    cudaGetSymbolAddress((void**)&pw3, g_wp3);
    cudaGetSymbolAddress((void**)&pw2, g_wp2);
    cudaGetSymbolAddress((void**)&pwL, g_wpL);

    const int SM_T3 = (2 * (128 * 52) + 2 * (16 * 136)) * 4;   // 70656
    const int SM_T1 = (2 * (128 * 20) + 2 * (16 * 136)) * 4;   // 37888

    cudaFuncSetAttribute((const void*)mmbf<1, true,  false>,
                         cudaFuncAttributeMaxDynamicSharedMemorySize, SM_T1);
    cudaFuncSetAttribute((const void*)mmbf<3, true,  false>,
                         cudaFuncAttributeMaxDynamicSharedMemorySize, SM_T3);
    cudaFuncSetAttribute((const void*)mmbf<1, false, false>,
                         cudaFuncAttributeMaxDynamicSharedMemorySize, SM_T1);
    cudaFuncSetAttribute((const void*)mmbf<1, false, true>,
                         cudaFuncAttributeMaxDynamicSharedMemorySize, SM_T1);

    // ---- weight pre-pack ----
    {
        int t0 = 6 * IXC * (FXC/2);
        pack1_kernel<<<(t0 + 255) / 256, 256>>>(w0s, pw0, t0);
        int t3 = 6 * IXC * 3 * (IXC/2);
        pack3_kernel<<<(t3 + 255) / 256, 256>>>(w1s, pw3);
        int t2 = 6 * FXC * (IXC/2);
        pack1_kernel<<<(t2 + 255) / 256, 256>>>(w2s, pw2, t2);
        int tL = CXC * IXC;
        pack1_kernel<<<(tL + 255) / 256, 256>>>(out_w, pwL, tL);
    }

    fe_kernel<<<1, 512>>>();
    {
        size_t n = (size_t)BXC * FXC * SXC;
        embed_kernel<<<(unsigned)((n + 255) / 256), 256>>>(inp, emb);
    }

    float* outs[3] = {pd, psc, psh};

    for (int l = 0; l < LXC; ++l) {
        for (int m = 0; m < 3; ++m) {
            int sl = l * 3 + m;
            const uint32_t* W0 = pw0 + (size_t)sl * IXC * (FXC/2);
            const uint32_t* W3 = pw3 + (size_t)sl * IXC * 3 * (IXC/2);
            const uint32_t* W2 = pw2 + (size_t)sl * FXC * (IXC/2);

            dim3 grid0(SXC / 128, IXC / 128, BXC);
            dim3 grid1(SXC / 128, IXC / 128, BXC);
            dim3 grid2(SXC / 128, FXC / 128, BXC);
            mmbf<1, true, false><<<grid0, 256, SM_T1>>>(W0, ph, py1, nullptr, IXC, FXC, SXC, FXC/2);
            mmbf<3, true, false><<<grid1, 256, SM_T3>>>(W3, py1, py2, nullptr, IXC, IXC, SXC, 3*(IXC/2));
            mmbf<1, false, false><<<grid2, 256, SM_T1>>>(W2, py2, outs[m], nullptr, FXC, IXC, SXC, IXC/2);
        }
        dim3 gridCB(SXC / 64, BXC);
        if (l == LXC - 1) combine2<true><<<gridCB, 256>>>();
        else              combine2<false><<<gridCB, 256>>>();
    }

    {
        dim3 gridC(SXC / 128, CXC / 128, BXC);
        mmbf<1, false, true><<<gridC, 256, SM_T1>>>(pwL, pstr, plog, out_b, CXC, 2 * FXC, SXC, IXC);
    }
    nll_kernel<<<BXC * SXC, 256>>>(tgt);
    reduce_kernel<<<1, 1024>>>(out);
}

// round 14
// speedup vs baseline: 9.5063x; 1.1141x over previous
#include <cuda_runtime.h>
#include <math.h>
#include <stdint.h>

#define BXC 2
#define SXC 2048
#define FXC 512
#define IXC 1024
#define KXC 3
#define LXC 2
#define CXC 256

#define PI_F 3.14159265358979323846f

// ---------------- scratch (device globals; no allocation allowed) ------------
__device__ float g_a  [BXC*FXC*SXC];
__device__ float g_b  [BXC*FXC*SXC];
__device__ float g_h  [BXC*FXC*SXC];
__device__ float g_y1 [3*BXC*IXC*SXC];          // [branch][b][i][s]
__device__ float g_y2 [3*BXC*IXC*SXC];          // [branch][b][i][s]
__device__ float g_ds3[3*BXC*FXC*SXC];          // [branch(d,sc,sh)][b][f][s]
__device__ float g_str[BXC*2*FXC*SXC];
__device__ float g_log[BXC*CXC*SXC];
__device__ float g_fe [FXC];
__device__ float g_nll[BXC*SXC];

// packed bf16x2 weights (k-pairs in one u32; lo = even k, hi = odd k)
__device__ uint32_t g_wp0[6 * IXC * (FXC/2)];      // conv0: [sl][m][kp]    (256/row)
__device__ uint32_t g_wp3[6 * IXC * 3 * (IXC/2)];  // conv1: [sl][m][t][kp] (1536/row)
__device__ uint32_t g_wp2[6 * FXC * (IXC/2)];      // conv2: [sl][m][kp]    (512/row)
__device__ uint32_t g_wpL[CXC * FXC];              // logits: [m][kp]       (512/row)

__device__ __forceinline__ uint32_t pk(float lo, float hi) {
    uint32_t r;
    asm("cvt.rn.bf16x2.f32 %0, %1, %2;" : "=r"(r) : "f"(hi), "f"(lo));
    return r;
}

// ---------------- fused pre-pack (+ feature embedding) -----------------------
__global__ void pack_all(const float* __restrict__ w1s,
                         const float* __restrict__ w0s,
                         const float* __restrict__ w2s,
                         const float* __restrict__ out_w) {
    const int T3 = 6 * IXC * 3 * (IXC/2);
    const int T0 = 6 * IXC * (FXC/2);
    const int T2 = 6 * FXC * (IXC/2);
    const int TL = CXC * FXC;              // 512 pairs per row x 256 rows
    int i = blockIdx.x * 256 + threadIdx.x;
    if (i < T3) {
        int kp = i & 511;
        int t  = (i >> 9) % 3;
        int m6 = i / 1536;
        const float* src = w1s + (size_t)m6 * (IXC * 3) + (size_t)kp * 6 + t;
        g_wp3[i] = pk(src[0], src[3]);
        return;
    }
    i -= T3;
    if (i < T0) {
        float2 v = *(const float2*)&w0s[(size_t)2 * i];
        g_wp0[i] = pk(v.x, v.y);
        return;
    }
    i -= T0;
    if (i < T2) {
        float2 v = *(const float2*)&w2s[(size_t)2 * i];
        g_wp2[i] = pk(v.x, v.y);
        return;
    }
    i -= T2;
    if (i < TL) {
        float2 v = *(const float2*)&out_w[(size_t)2 * i];
        g_wpL[i] = pk(v.x, v.y);
        return;
    }
    i -= TL;
    if (i < FXC) {
        float ff = (float)i + 1.0f;
        float additive = fmodf(ff, 2.0f);
        float g = (ff - additive) * 0.5f;
        g = g * (8.0f / (float)FXC) - logf((float)CXC / (2.0f * PI_F));
        g_fe[i] = expf(g) + additive * PI_F;
    }
}

// ---------------- embedding gather (also builds h = b + fe) -------------------
__global__ void embed_kernel(const int* __restrict__ inp,
                             const float* __restrict__ emb) {
    size_t idx = (size_t)blockIdx.x * blockDim.x + threadIdx.x;
    if (idx >= (size_t)BXC * FXC * SXC) return;
    int s = (int)(idx % SXC);
    int f = (int)((idx / SXC) % FXC);
    int b = (int)(idx / ((size_t)SXC * FXC));
    int tok = inp[b * SXC + s];
    float av = emb[(size_t)tok * (2 * FXC) + f];
    float bv = emb[(size_t)tok * (2 * FXC) + FXC + f];
    g_a[idx] = av;
    g_b[idx] = bv;
    g_h[idx] = bv + g_fe[f];
    (void)s;
}

// ================= bf16 tensor-core conv-GEMM ================================
#define CP16(d, s)  asm volatile("cp.async.cg.shared.global [%0], [%1], 16;" :: "r"(d), "l"(s))
#define CPCOMMIT()  asm volatile("cp.async.commit_group;")
#define CPWAIT0()   asm volatile("cp.async.wait_group 0;")

__device__ __forceinline__ void mma_bf16(float* c, const uint32_t* a, const uint32_t* b) {
    asm volatile(
        "mma.sync.aligned.m16n8k16.row.col.f32.bf16.bf16.f32 "
        "{%0,%1,%2,%3}, {%4,%5,%6,%7}, {%8,%9}, {%0,%1,%2,%3};"
        : "+f"(c[0]), "+f"(c[1]), "+f"(c[2]), "+f"(c[3])
        : "r"(a[0]), "r"(a[1]), "r"(a[2]), "r"(a[3]), "r"(b[0]), "r"(b[1]));
}

// z = blockIdx.z indexes (branch*BXC + b) for batched convs, or just b.
// X is [z][Kd][N]. A row stride ApS (u32); per-branch A offset AzStride (u32).
// YSPLIT: Y is [branch][BXC][1024][N] with m spanning 3*1024.
template <int TAPS, bool RELU, bool BIAS, bool YSPLIT>
__global__ __launch_bounds__(256, 2)
void mmbf(const uint32_t* __restrict__ Ap,
          const float* __restrict__ X,
          float* __restrict__ Y,
          const float* __restrict__ bias,
          int M, int Kd, int N, int ApS, size_t AzStride) {
    constexpr int AC   = 16 * TAPS;
    constexpr int AST  = AC + 4;
    constexpr int XOFF = 4;
    constexpr int XST  = 136;
    constexpr int ASZ  = 128 * AST;
    constexpr int XSZ  = 16 * XST;

    extern __shared__ uint32_t sm[];
    uint32_t* As0 = sm;
    uint32_t* As1 = sm + ASZ;
    uint32_t* Xs0 = sm + 2 * ASZ;
    uint32_t* Xs1 = sm + 2 * ASZ + XSZ;

    const int z   = blockIdx.z;
    const int m0g = blockIdx.y * 128;
    const int n0  = blockIdx.x * 128;
    if (AzStride) Ap += (size_t)(z >> 1) * AzStride;
    X += (size_t)z * (size_t)Kd * N;
    int m0;
    if (YSPLIT) {
        Y += ((size_t)(m0g >> 10) * BXC + z) * (size_t)1024 * N;
        m0 = m0g & 1023;
    } else {
        Y += (size_t)z * (size_t)M * N;
        m0 = m0g;
    }

    const int tid  = threadIdx.x;
    const int lane = tid & 31;
    const int w    = tid >> 5;
    const int wM   = (w >> 2) * 64;
    const int wN   = (w & 3) * 32;
    const int g    = lane >> 2;
    const int tig  = lane & 3;

    const int am   = tid >> 1;
    const int ah   = tid & 1;
    const uint32_t* agp = Ap + (size_t)(m0g + am) * ApS + ah * 8;
    uint32_t asm0 = (uint32_t)__cvta_generic_to_shared(As0 + am * AST + ah * 8);
    uint32_t asm1 = (uint32_t)__cvta_generic_to_shared(As1 + am * AST + ah * 8);

    const int kpa = tid >> 5;
    const int nqa = tid & 31;
    const int kpb = kpa + 8;
    const float* xga = X + (size_t)(2 * kpa) * N + n0 + 4 * nqa;
    const float* xgb = X + (size_t)(2 * kpb) * N + n0 + 4 * nqa;

    float c[4][4][4];
#pragma unroll
    for (int i = 0; i < 4; i++)
#pragma unroll
        for (int j = 0; j < 4; j++)
#pragma unroll
            for (int q = 0; q < 4; q++) c[i][j][q] = 0.0f;

    uint32_t xu[2][4];
    uint32_t xh[2];

    auto ldA = [&](int st, int ck) {
        const uint32_t* s0 = agp + (size_t)ck * 16;
        uint32_t d0 = (st ? asm1 : asm0);
#pragma unroll
        for (int t = 0; t < TAPS; t++) {
            CP16(d0 + t * 16 * 4, s0 + t * (Kd / 2));
            CP16(d0 + t * 16 * 4 + 16, s0 + t * (Kd / 2) + 4);
        }
    };

    auto ldX = [&](int ck) {
        const float* p0 = xga + (size_t)(ck * 32) * N;
        const float* p1 = xgb + (size_t)(ck * 32) * N;
        float4 r0 = *(const float4*)p0;
        float4 r1 = *(const float4*)(p0 + N);
        xu[0][0] = pk(r0.x, r1.x); xu[0][1] = pk(r0.y, r1.y);
        xu[0][2] = pk(r0.z, r1.z); xu[0][3] = pk(r0.w, r1.w);
        float4 r2 = *(const float4*)p1;
        float4 r3 = *(const float4*)(p1 + N);
        xu[1][0] = pk(r2.x, r3.x); xu[1][1] = pk(r2.y, r3.y);
        xu[1][2] = pk(r2.z, r3.z); xu[1][3] = pk(r2.w, r3.w);
        if (TAPS == 3) {
            if (tid < 16) {
                if (n0 > 0) {
                    const float* h0 = X + (size_t)(ck * 32 + 2 * tid) * N + n0 - 2;
                    const float* h1 = h0 + N;
                    xh[0] = pk(h0[0], h1[0]);
                    xh[1] = pk(h0[1], h1[1]);
                } else {
                    xh[0] = 0u; xh[1] = 0u;
                }
            }
        }
    };

    auto stX = [&](int st) {
        uint32_t* Xb = st ? Xs1 : Xs0;
        *(uint4*)&Xb[kpa * XST + XOFF + 4 * nqa] = make_uint4(xu[0][0], xu[0][1], xu[0][2], xu[0][3]);
        *(uint4*)&Xb[kpb * XST + XOFF + 4 * nqa] = make_uint4(xu[1][0], xu[1][1], xu[1][2], xu[1][3]);
        if (TAPS == 3) {
            if (tid < 16) {
                Xb[tid * XST + 2] = xh[0];
                Xb[tid * XST + 3] = xh[1];
            }
        }
    };

    auto compute = [&](int st) {
        const uint32_t* Ab = st ? As1 : As0;
        const uint32_t* Xb = st ? Xs1 : Xs0;
#pragma unroll
        for (int t = 0; t < TAPS; t++) {
#pragma unroll
            for (int s = 0; s < 2; s++) {
                uint32_t af[4][4];
#pragma unroll
                for (int i = 0; i < 4; i++) {
                    const uint32_t* p = Ab + (wM + i * 16 + g) * AST + t * 16 + s * 8 + tig;
                    af[i][0] = p[0];
                    af[i][1] = p[8 * AST];
                    af[i][2] = p[4];
                    af[i][3] = p[8 * AST + 4];
                }
                uint32_t bf[4][2];
                const uint32_t* q0 = Xb + (s * 8 + tig) * XST + XOFF + (t - (TAPS - 1)) + wN + g;
#pragma unroll
                for (int j = 0; j < 4; j++) {
                    bf[j][0] = q0[j * 8];
                    bf[j][1] = q0[4 * XST + j * 8];
                }
#pragma unroll
                for (int i = 0; i < 4; i++)
#pragma unroll
                    for (int j = 0; j < 4; j++)
                        mma_bf16(c[i][j], af[i], bf[j]);
            }
        }
    };

    const int NC = Kd / 32;
    ldA(0, 0); CPCOMMIT();
    ldX(0); stX(0);
    CPWAIT0();
    __syncthreads();

    for (int cc = 0; cc < NC; cc++) {
        int nx = cc + 1;
        if (nx < NC) {
            ldA(nx & 1, nx); CPCOMMIT();
            ldX(nx);
        }
        compute(cc & 1);
        if (nx < NC) {
            stX(nx & 1);
            CPWAIT0();
        }
        __syncthreads();
    }

#pragma unroll
    for (int i = 0; i < 4; i++) {
        int m = m0 + wM + i * 16 + g;
        float bi0 = BIAS ? bias[m] : 0.0f;
        float bi1 = BIAS ? bias[m + 8] : 0.0f;
#pragma unroll
        for (int j = 0; j < 4; j++) {
            int n = n0 + wN + j * 8 + 2 * tig;
            float2 v0 = make_float2(c[i][j][0] + bi0, c[i][j][1] + bi0);
            float2 v1 = make_float2(c[i][j][2] + bi1, c[i][j][3] + bi1);
            if (RELU) {
                v0.x = fmaxf(v0.x, 0.0f); v0.y = fmaxf(v0.y, 0.0f);
                v1.x = fmaxf(v1.x, 0.0f); v1.y = fmaxf(v1.y, 0.0f);
            }
            *(float2*)&Y[(size_t)m * N + n]       = v0;
            *(float2*)&Y[(size_t)(m + 8) * N + n] = v1;
        }
    }
}

// ========== combine: coalesced two-pass, thread-per-s-column ==================
template <bool LAST>
__global__ __launch_bounds__(256)
void combine2() {
    __shared__ float sTd[4][64], sSu[4][64], sSuu[4][64];
    __shared__ float sSusc[4][64], sSsc[4][64], sSscsc[4][64];
    __shared__ float sOff[4][64], sMean[64], sInvd[64];

    const int scol = threadIdx.x & 63;
    const int part = threadIdx.x >> 6;
    const int b = blockIdx.y;
    const int s = blockIdx.x * 64 + scol;
    const float inv = 1.0f / (float)(s + 1);
    const size_t base = (size_t)b * FXC * SXC + s;
    const size_t DS1 = (size_t)BXC * FXC * SXC;
    const int f0 = part * 128;

    float cum = 0.0f, Su = 0.0f, Suu = 0.0f, Susc = 0.0f, Ssc = 0.0f, Sscsc = 0.0f;
#pragma unroll 4
    for (int j = 0; j < 128; j++) {
        size_t id = base + (size_t)(f0 + j) * SXC;
        float dv = g_ds3[id];
        float sc = g_ds3[id + DS1];
        float sh = g_ds3[id + 2 * DS1];
        cum += dv;
        float u = cum * inv * sc + sh;
        Su += u; Suu += u * u; Susc += u * sc;
        Ssc += sc; Sscsc += sc * sc;
    }
    sTd[part][scol] = cum;
    sSu[part][scol] = Su;     sSuu[part][scol] = Suu;
    sSusc[part][scol] = Susc; sSsc[part][scol] = Ssc;
    sSscsc[part][scol] = Sscsc;
    __syncthreads();

    if (part == 0) {
        float off = 0.0f, S1 = 0.0f, S2 = 0.0f;
#pragma unroll
        for (int p = 0; p < 4; p++) {
            sOff[p][scol] = off;
            float cp = off * inv;
            S1 += sSu[p][scol] + cp * sSsc[p][scol];
            S2 += sSuu[p][scol] + 2.0f * cp * sSusc[p][scol] + cp * cp * sSscsc[p][scol];
            off += sTd[p][scol];
        }
        float mean = S1 * (1.0f / (float)FXC);
        float ssq = fmaxf(S2 - S1 * mean, 0.0f);
        float denom = sqrtf(ssq) * rsqrtf((float)FXC) + 1e-5f;
        sMean[scol] = mean;
        sInvd[scol] = 1.0f / denom;
    }
    __syncthreads();

    const float INIT_SCALE = 0.7071067811865476f;
    const float BETA = 0.99f;
    float off  = sOff[part][scol];
    float mean = sMean[scol];
    float invd = sInvd[scol];
    float cum2 = off;
#pragma unroll 4
    for (int j = 0; j < 128; j++) {
        int f = f0 + j;
        size_t id = base + (size_t)f * SXC;
        float dv = g_ds3[id];
        float sc = g_ds3[id + DS1];
        float sh = g_ds3[id + 2 * DS1];
        cum2 += dv;
        float val = cum2 * inv * sc + sh;
        float cell = (val - mean) * invd * INIT_SCALE;
        float cnew = BETA * g_a[id] + (1.0f - BETA) * cell;
        g_a[id] = cnew;
        float nb = g_b[id] + cnew;
        g_b[id] = nb;
        if (LAST) {
            size_t sb = ((size_t)b * 2 * FXC + f) * SXC + s;
            g_str[sb] = cnew;
            g_str[sb + (size_t)FXC * SXC] = nb;
        } else {
            g_h[id] = nb + g_fe[f];
        }
    }
}

// ---------------- per-position NLL -------------------------------------------
__global__ void nll_kernel(const int* __restrict__ tgt) {
    int bs = blockIdx.x;
    int b = bs >> 11;
    int s = bs & 2047;
    int c = threadIdx.x;
    float x = g_log[((size_t)b * CXC + c) * SXC + s];

    int lane = c & 31, wid = c >> 5;
    __shared__ float red[8];
    __shared__ float bc[2];
    __shared__ float tval;

    float m = x;
#pragma unroll
    for (int o = 16; o > 0; o >>= 1) m = fmaxf(m, __shfl_xor_sync(0xffffffffu, m, o));
    if (lane == 0) red[wid] = m;
    __syncthreads();
    if (c == 0) {
        float t2 = red[0];
        for (int i = 1; i < 8; i++) t2 = fmaxf(t2, red[i]);
        bc[0] = t2;
    }
    __syncthreads();
    float e = expf(x - bc[0]);
#pragma unroll
    for (int o = 16; o > 0; o >>= 1) e += __shfl_xor_sync(0xffffffffu, e, o);
    __syncthreads();
    if (lane == 0) red[wid] = e;
    int tv = tgt[b * SXC + s];
    if (c == tv) tval = x;
    __syncthreads();
    if (c == 0) {
        float t2 = 0.0f;
        for (int i = 0; i < 8; i++) t2 += red[i];
        float lse = bc[0] + logf(t2);
        g_nll[bs] = lse - tval;
    }
}

// ---------------- deterministic final mean -----------------------------------
__global__ void reduce_kernel(float* __restrict__ out) {
    __shared__ float sh[1024];
    int t = threadIdx.x;
    float s = 0.0f;
    for (int i = t; i < BXC * SXC; i += 1024) s += g_nll[i];
    sh[t] = s;
    __syncthreads();
    for (int o = 512; o > 0; o >>= 1) {
        if (t < o) sh[t] += sh[t + o];
        __syncthreads();
    }
    if (t == 0) out[0] = sh[0] / (float)(BXC * SXC);
}

// ---------------- host orchestration -----------------------------------------
extern "C" void kernel_launch(void* const* d_in, const int* in_sizes, int n_in,
                              void* d_out, int out_size) {
    const int*   inp   = (const int*)d_in[0];
    const int*   tgt   = (const int*)d_in[1];
    const float* emb   = (const float*)d_in[2];
    const float* w0s   = (const float*)d_in[3];
    const float* w1s   = (const float*)d_in[4];
    const float* w2s   = (const float*)d_in[5];
    const float* out_w = (const float*)d_in[6];
    const float* out_b = (const float*)d_in[7];
    float* out = (float*)d_out;

    float *ph, *py1, *py2, *pds, *pstr, *plog;
    uint32_t *pw0, *pw3, *pw2, *pwL;
    cudaGetSymbolAddress((void**)&ph,  g_h);
    cudaGetSymbolAddress((void**)&py1, g_y1);
    cudaGetSymbolAddress((void**)&py2, g_y2);
    cudaGetSymbolAddress((void**)&pds, g_ds3);
    cudaGetSymbolAddress((void**)&pstr, g_str);
    cudaGetSymbolAddress((void**)&plog, g_log);
    cudaGetSymbolAddress((void**)&pw0, g_wp0);
    cudaGetSymbolAddress((void**)&pw3, g_wp3);
    cudaGetSymbolAddress((void**)&pw2, g_wp2);
    cudaGetSymbolAddress((void**)&pwL, g_wpL);

    const int SM_T3 = (2 * (128 * 52) + 2 * (16 * 136)) * 4;   // 70656
    const int SM_T1 = (2 * (128 * 20) + 2 * (16 * 136)) * 4;   // 37888

    cudaFuncSetAttribute((const void*)mmbf<1, true,  false, true>,
                         cudaFuncAttributeMaxDynamicSharedMemorySize, SM_T1);
    cudaFuncSetAttribute((const void*)mmbf<3, true,  false, false>,
                         cudaFuncAttributeMaxDynamicSharedMemorySize, SM_T3);
    cudaFuncSetAttribute((const void*)mmbf<1, false, false, false>,
                         cudaFuncAttributeMaxDynamicSharedMemorySize, SM_T1);
    cudaFuncSetAttribute((const void*)mmbf<1, false, true,  false>,
                         cudaFuncAttributeMaxDynamicSharedMemorySize, SM_T1);

    // ---- launch 1: all weight packs + fe ----
    {
        int total = 6*IXC*3*(IXC/2) + 6*IXC*(FXC/2) + 6*FXC*(IXC/2) + CXC*FXC + FXC;
        pack_all<<<(total + 255) / 256, 256>>>(w1s, w0s, w2s, out_w);
    }
    // ---- launch 2: embedding ----
    {
        size_t n = (size_t)BXC * FXC * SXC;
        embed_kernel<<<(unsigned)((n + 255) / 256), 256>>>(inp, emb);
    }

    const size_t AzS3 = (size_t)IXC * 3 * (IXC/2);
    const size_t AzS2 = (size_t)FXC * (IXC/2);

    for (int l = 0; l < LXC; ++l) {
        const uint32_t* W0 = pw0 + (size_t)l * 3 * IXC * (FXC/2);
        const uint32_t* W3 = pw3 + (size_t)l * 3 * AzS3;
        const uint32_t* W2 = pw2 + (size_t)l * 3 * AzS2;

        // conv0: all 3 branches merged, M = 3072, Y split to [branch][b][i][s]
        dim3 grid0(SXC / 128, (3 * IXC) / 128, BXC);            // 16 x 24 x 2
        mmbf<1, true, false, true><<<grid0, 256, SM_T1>>>(
            W0, ph, py1, nullptr, 3 * IXC, FXC, SXC, FXC/2, 0);
        // conv1: causal k=3, z-batched over branch*B + b
        dim3 grid1(SXC / 128, IXC / 128, 3 * BXC);              // 16 x 8 x 6
        mmbf<3, true, false, false><<<grid1, 256, SM_T3>>>(
            W3, py1, py2, nullptr, IXC, IXC, SXC, 3 * (IXC/2), AzS3);
        // conv2: z-batched, writes [branch][b][f][s] into g_ds3
        dim3 grid2(SXC / 128, FXC / 128, 3 * BXC);              // 16 x 4 x 6
        mmbf<1, false, false, false><<<grid2, 256, SM_T1>>>(
            W2, py2, pds, nullptr, FXC, IXC, SXC, IXC/2, AzS2);

        dim3 gridCB(SXC / 64, BXC);
        if (l == LXC - 1) combine2<true><<<gridCB, 256>>>();
        else              combine2<false><<<gridCB, 256>>>();
    }

    {
        dim3 gridC(SXC / 128, CXC / 128, BXC);                  // 16 x 2 x 2
        mmbf<1, false, true, false><<<gridC, 256, SM_T1>>>(
            pwL, pstr, plog, out_b, CXC, 2 * FXC, SXC, FXC, 0);
    }
    nll_kernel<<<BXC * SXC, 256>>>(tgt);
    reduce_kernel<<<1, 1024>>>(out);
}

// round 15
// speedup vs baseline: 9.5144x; 1.0008x over previous
#include <cuda_runtime.h>
#include <math.h>
#include <stdint.h>

#define BXC 2
#define SXC 2048
#define FXC 512
#define IXC 1024
#define KXC 3
#define LXC 2
#define CXC 256

#define PI_F 3.14159265358979323846f

// ---------------- scratch (device globals; no allocation allowed) ------------
__device__ float g_a  [BXC*FXC*SXC];
__device__ float g_b  [BXC*FXC*SXC];
__device__ float g_h  [BXC*FXC*SXC];
__device__ float g_y1 [3*BXC*IXC*SXC];          // [branch][b][i][s]
__device__ float g_y2 [3*BXC*IXC*SXC];          // [branch][b][i][s]
__device__ float g_ds3[3*BXC*FXC*SXC];          // [branch(d,sc,sh)][b][f][s]
__device__ float g_str[BXC*2*FXC*SXC];
__device__ float g_log[BXC*CXC*SXC];
__device__ float g_fe [FXC];
__device__ float g_nll[BXC*SXC];

// packed bf16x2 weights (k-pairs in one u32; lo = even k, hi = odd k)
__device__ uint32_t g_wp0[6 * IXC * (FXC/2)];      // conv0: [sl][m][kp]    (256/row)
__device__ uint32_t g_wp3[6 * IXC * 3 * (IXC/2)];  // conv1: [sl][m][t][kp] (1536/row)
__device__ uint32_t g_wp2[6 * FXC * (IXC/2)];      // conv2: [sl][m][kp]    (512/row)
__device__ uint32_t g_wpL[CXC * FXC];              // logits: [m][kp]       (512/row)

__device__ __forceinline__ uint32_t pk(float lo, float hi) {
    uint32_t r;
    asm("cvt.rn.bf16x2.f32 %0, %1, %2;" : "=r"(r) : "f"(hi), "f"(lo));
    return r;
}

// ---------------- fused pre-pack (+ feature embedding) -----------------------
__global__ void pack_all(const float* __restrict__ w1s,
                         const float* __restrict__ w0s,
                         const float* __restrict__ w2s,
                         const float* __restrict__ out_w) {
    const int T3 = 6 * IXC * 3 * (IXC/2);
    const int T0 = 6 * IXC * (FXC/2);
    const int T2 = 6 * FXC * (IXC/2);
    const int TL = CXC * FXC;              // 512 pairs per row x 256 rows
    int i = blockIdx.x * 256 + threadIdx.x;
    if (i < T3) {
        int kp = i & 511;
        int t  = (i >> 9) % 3;
        int m6 = i / 1536;
        const float* src = w1s + (size_t)m6 * (IXC * 3) + (size_t)kp * 6 + t;
        g_wp3[i] = pk(src[0], src[3]);
        return;
    }
    i -= T3;
    if (i < T0) {
        float2 v = *(const float2*)&w0s[(size_t)2 * i];
        g_wp0[i] = pk(v.x, v.y);
        return;
    }
    i -= T0;
    if (i < T2) {
        float2 v = *(const float2*)&w2s[(size_t)2 * i];
        g_wp2[i] = pk(v.x, v.y);
        return;
    }
    i -= T2;
    if (i < TL) {
        float2 v = *(const float2*)&out_w[(size_t)2 * i];
        g_wpL[i] = pk(v.x, v.y);
        return;
    }
    i -= TL;
    if (i < FXC) {
        float ff = (float)i + 1.0f;
        float additive = fmodf(ff, 2.0f);
        float g = (ff - additive) * 0.5f;
        g = g * (8.0f / (float)FXC) - logf((float)CXC / (2.0f * PI_F));
        g_fe[i] = expf(g) + additive * PI_F;
    }
}

// ---------------- embedding gather (also builds h = b + fe) -------------------
__global__ void embed_kernel(const int* __restrict__ inp,
                             const float* __restrict__ emb) {
    size_t idx = (size_t)blockIdx.x * blockDim.x + threadIdx.x;
    if (idx >= (size_t)BXC * FXC * SXC) return;
    int s = (int)(idx % SXC);
    int f = (int)((idx / SXC) % FXC);
    int b = (int)(idx / ((size_t)SXC * FXC));
    int tok = inp[b * SXC + s];
    float av = emb[(size_t)tok * (2 * FXC) + f];
    float bv = emb[(size_t)tok * (2 * FXC) + FXC + f];
    g_a[idx] = av;
    g_b[idx] = bv;
    g_h[idx] = bv + g_fe[f];
    (void)s;
}

// ================= bf16 tensor-core conv-GEMM ================================
#define CP16(d, s)  asm volatile("cp.async.cg.shared.global [%0], [%1], 16;" :: "r"(d), "l"(s))
#define CPCOMMIT()  asm volatile("cp.async.commit_group;")
#define CPWAIT0()   asm volatile("cp.async.wait_group 0;")

__device__ __forceinline__ void mma_bf16(float* c, const uint32_t* a, const uint32_t* b) {
    asm volatile(
        "mma.sync.aligned.m16n8k16.row.col.f32.bf16.bf16.f32 "
        "{%0,%1,%2,%3}, {%4,%5,%6,%7}, {%8,%9}, {%0,%1,%2,%3};"
        : "+f"(c[0]), "+f"(c[1]), "+f"(c[2]), "+f"(c[3])
        : "r"(a[0]), "r"(a[1]), "r"(a[2]), "r"(a[3]), "r"(b[0]), "r"(b[1]));
}

// z = blockIdx.z indexes (branch*BXC + b) for batched convs, or just b.
// X is [z][Kd][N]. A row stride ApS (u32); per-branch A offset AzStride (u32).
// YSPLIT: Y is [branch][BXC][1024][N] with m spanning 3*1024.
template <int TAPS, bool RELU, bool BIAS, bool YSPLIT>
__global__ __launch_bounds__(256, 2)
void mmbf(const uint32_t* __restrict__ Ap,
          const float* __restrict__ X,
          float* __restrict__ Y,
          const float* __restrict__ bias,
          int M, int Kd, int N, int ApS, size_t AzStride) {
    constexpr int AC   = 16 * TAPS;
    constexpr int AST  = AC + 4;
    constexpr int XOFF = 4;
    constexpr int XST  = 136;
    constexpr int ASZ  = 128 * AST;
    constexpr int XSZ  = 16 * XST;

    extern __shared__ uint32_t sm[];
    uint32_t* As0 = sm;
    uint32_t* As1 = sm + ASZ;
    uint32_t* Xs0 = sm + 2 * ASZ;
    uint32_t* Xs1 = sm + 2 * ASZ + XSZ;

    const int z   = blockIdx.z;
    const int m0g = blockIdx.y * 128;
    const int n0  = blockIdx.x * 128;
    if (AzStride) Ap += (size_t)(z >> 1) * AzStride;
    X += (size_t)z * (size_t)Kd * N;
    int m0;
    if (YSPLIT) {
        Y += ((size_t)(m0g >> 10) * BXC + z) * (size_t)1024 * N;
        m0 = m0g & 1023;
    } else {
        Y += (size_t)z * (size_t)M * N;
        m0 = m0g;
    }

    const int tid  = threadIdx.x;
    const int lane = tid & 31;
    const int w    = tid >> 5;
    const int wM   = (w >> 2) * 64;
    const int wN   = (w & 3) * 32;
    const int g    = lane >> 2;
    const int tig  = lane & 3;

    const int am   = tid >> 1;
    const int ah   = tid & 1;
    const uint32_t* agp = Ap + (size_t)(m0g + am) * ApS + ah * 8;
    uint32_t asm0 = (uint32_t)__cvta_generic_to_shared(As0 + am * AST + ah * 8);
    uint32_t asm1 = (uint32_t)__cvta_generic_to_shared(As1 + am * AST + ah * 8);

    const int kpa = tid >> 5;
    const int nqa = tid & 31;
    const int kpb = kpa + 8;
    const float* xga = X + (size_t)(2 * kpa) * N + n0 + 4 * nqa;
    const float* xgb = X + (size_t)(2 * kpb) * N + n0 + 4 * nqa;

    float c[4][4][4];
#pragma unroll
    for (int i = 0; i < 4; i++)
#pragma unroll
        for (int j = 0; j < 4; j++)
#pragma unroll
            for (int q = 0; q < 4; q++) c[i][j][q] = 0.0f;

    uint32_t xu[2][4];
    uint32_t xh[2];

    auto ldA = [&](int st, int ck) {
        const uint32_t* s0 = agp + (size_t)ck * 16;
        uint32_t d0 = (st ? asm1 : asm0);
#pragma unroll
        for (int t = 0; t < TAPS; t++) {
            CP16(d0 + t * 16 * 4, s0 + t * (Kd / 2));
            CP16(d0 + t * 16 * 4 + 16, s0 + t * (Kd / 2) + 4);
        }
    };

    auto ldX = [&](int ck) {
        const float* p0 = xga + (size_t)(ck * 32) * N;
        const float* p1 = xgb + (size_t)(ck * 32) * N;
        float4 r0 = *(const float4*)p0;
        float4 r1 = *(const float4*)(p0 + N);
        xu[0][0] = pk(r0.x, r1.x); xu[0][1] = pk(r0.y, r1.y);
        xu[0][2] = pk(r0.z, r1.z); xu[0][3] = pk(r0.w, r1.w);
        float4 r2 = *(const float4*)p1;
        float4 r3 = *(const float4*)(p1 + N);
        xu[1][0] = pk(r2.x, r3.x); xu[1][1] = pk(r2.y, r3.y);
        xu[1][2] = pk(r2.z, r3.z); xu[1][3] = pk(r2.w, r3.w);
        if (TAPS == 3) {
            if (tid < 16) {
                if (n0 > 0) {
                    const float* h0 = X + (size_t)(ck * 32 + 2 * tid) * N + n0 - 2;
                    const float* h1 = h0 + N;
                    xh[0] = pk(h0[0], h1[0]);
                    xh[1] = pk(h0[1], h1[1]);
                } else {
                    xh[0] = 0u; xh[1] = 0u;
                }
            }
        }
    };

    auto stX = [&](int st) {
        uint32_t* Xb = st ? Xs1 : Xs0;
        *(uint4*)&Xb[kpa * XST + XOFF + 4 * nqa] = make_uint4(xu[0][0], xu[0][1], xu[0][2], xu[0][3]);
        *(uint4*)&Xb[kpb * XST + XOFF + 4 * nqa] = make_uint4(xu[1][0], xu[1][1], xu[1][2], xu[1][3]);
        if (TAPS == 3) {
            if (tid < 16) {
                Xb[tid * XST + 2] = xh[0];
                Xb[tid * XST + 3] = xh[1];
            }
        }
    };

    auto compute = [&](int st) {
        const uint32_t* Ab = st ? As1 : As0;
        const uint32_t* Xb = st ? Xs1 : Xs0;
#pragma unroll
        for (int t = 0; t < TAPS; t++) {
#pragma unroll
            for (int s = 0; s < 2; s++) {
                uint32_t af[4][4];
#pragma unroll
                for (int i = 0; i < 4; i++) {
                    const uint32_t* p = Ab + (wM + i * 16 + g) * AST + t * 16 + s * 8 + tig;
                    af[i][0] = p[0];
                    af[i][1] = p[8 * AST];
                    af[i][2] = p[4];
                    af[i][3] = p[8 * AST + 4];
                }
                uint32_t bf[4][2];
                const uint32_t* q0 = Xb + (s * 8 + tig) * XST + XOFF + (t - (TAPS - 1)) + wN + g;
#pragma unroll
                for (int j = 0; j < 4; j++) {
                    bf[j][0] = q0[j * 8];
                    bf[j][1] = q0[4 * XST + j * 8];
                }
#pragma unroll
                for (int i = 0; i < 4; i++)
#pragma unroll
                    for (int j = 0; j < 4; j++)
                        mma_bf16(c[i][j], af[i], bf[j]);
            }
        }
    };

    const int NC = Kd / 32;
    ldA(0, 0); CPCOMMIT();
    ldX(0); stX(0);
    CPWAIT0();
    __syncthreads();

    for (int cc = 0; cc < NC; cc++) {
        int nx = cc + 1;
        if (nx < NC) {
            ldA(nx & 1, nx); CPCOMMIT();
            ldX(nx);
        }
        compute(cc & 1);
        if (nx < NC) {
            stX(nx & 1);
            CPWAIT0();
        }
        __syncthreads();
    }

#pragma unroll
    for (int i = 0; i < 4; i++) {
        int m = m0 + wM + i * 16 + g;
        float bi0 = BIAS ? bias[m] : 0.0f;
        float bi1 = BIAS ? bias[m + 8] : 0.0f;
#pragma unroll
        for (int j = 0; j < 4; j++) {
            int n = n0 + wN + j * 8 + 2 * tig;
            float2 v0 = make_float2(c[i][j][0] + bi0, c[i][j][1] + bi0);
            float2 v1 = make_float2(c[i][j][2] + bi1, c[i][j][3] + bi1);
            if (RELU) {
                v0.x = fmaxf(v0.x, 0.0f); v0.y = fmaxf(v0.y, 0.0f);
                v1.x = fmaxf(v1.x, 0.0f); v1.y = fmaxf(v1.y, 0.0f);
            }
            *(float2*)&Y[(size_t)m * N + n]       = v0;
            *(float2*)&Y[(size_t)(m + 8) * N + n] = v1;
        }
    }
}

// ========== combine: coalesced two-pass, thread-per-s-column ==================
template <bool LAST>
__global__ __launch_bounds__(256)
void combine2() {
    __shared__ float sTd[4][64], sSu[4][64], sSuu[4][64];
    __shared__ float sSusc[4][64], sSsc[4][64], sSscsc[4][64];
    __shared__ float sOff[4][64], sMean[64], sInvd[64];

    const int scol = threadIdx.x & 63;
    const int part = threadIdx.x >> 6;
    const int b = blockIdx.y;
    const int s = blockIdx.x * 64 + scol;
    const float inv = 1.0f / (float)(s + 1);
    const size_t base = (size_t)b * FXC * SXC + s;
    const size_t DS1 = (size_t)BXC * FXC * SXC;
    const int f0 = part * 128;

    float cum = 0.0f, Su = 0.0f, Suu = 0.0f, Susc = 0.0f, Ssc = 0.0f, Sscsc = 0.0f;
#pragma unroll 4
    for (int j = 0; j < 128; j++) {
        size_t id = base + (size_t)(f0 + j) * SXC;
        float dv = g_ds3[id];
        float sc = g_ds3[id + DS1];
        float sh = g_ds3[id + 2 * DS1];
        cum += dv;
        float u = cum * inv * sc + sh;
        Su += u; Suu += u * u; Susc += u * sc;
        Ssc += sc; Sscsc += sc * sc;
    }
    sTd[part][scol] = cum;
    sSu[part][scol] = Su;     sSuu[part][scol] = Suu;
    sSusc[part][scol] = Susc; sSsc[part][scol] = Ssc;
    sSscsc[part][scol] = Sscsc;
    __syncthreads();

    if (part == 0) {
        float off = 0.0f, S1 = 0.0f, S2 = 0.0f;
#pragma unroll
        for (int p = 0; p < 4; p++) {
            sOff[p][scol] = off;
            float cp = off * inv;
            S1 += sSu[p][scol] + cp * sSsc[p][scol];
            S2 += sSuu[p][scol] + 2.0f * cp * sSusc[p][scol] + cp * cp * sSscsc[p][scol];
            off += sTd[p][scol];
        }
        float mean = S1 * (1.0f / (float)FXC);
        float ssq = fmaxf(S2 - S1 * mean, 0.0f);
        float denom = sqrtf(ssq) * rsqrtf((float)FXC) + 1e-5f;
        sMean[scol] = mean;
        sInvd[scol] = 1.0f / denom;
    }
    __syncthreads();

    const float INIT_SCALE = 0.7071067811865476f;
    const float BETA = 0.99f;
    float off  = sOff[part][scol];
    float mean = sMean[scol];
    float invd = sInvd[scol];
    float cum2 = off;
#pragma unroll 4
    for (int j = 0; j < 128; j++) {
        int f = f0 + j;
        size_t id = base + (size_t)f * SXC;
        float dv = g_ds3[id];
        float sc = g_ds3[id + DS1];
        float sh = g_ds3[id + 2 * DS1];
        cum2 += dv;
        float val = cum2 * inv * sc + sh;
        float cell = (val - mean) * invd * INIT_SCALE;
        float cnew = BETA * g_a[id] + (1.0f - BETA) * cell;
        g_a[id] = cnew;
        float nb = g_b[id] + cnew;
        g_b[id] = nb;
        if (LAST) {
            size_t sb = ((size_t)b * 2 * FXC + f) * SXC + s;
            g_str[sb] = cnew;
            g_str[sb + (size_t)FXC * SXC] = nb;
        } else {
            g_h[id] = nb + g_fe[f];
        }
    }
}

// ---------------- per-position NLL -------------------------------------------
__global__ void nll_kernel(const int* __restrict__ tgt) {
    int bs = blockIdx.x;
    int b = bs >> 11;
    int s = bs & 2047;
    int c = threadIdx.x;
    float x = g_log[((size_t)b * CXC + c) * SXC + s];

    int lane = c & 31, wid = c >> 5;
    __shared__ float red[8];
    __shared__ float bc[2];
    __shared__ float tval;

    float m = x;
#pragma unroll
    for (int o = 16; o > 0; o >>= 1) m = fmaxf(m, __shfl_xor_sync(0xffffffffu, m, o));
    if (lane == 0) red[wid] = m;
    __syncthreads();
    if (c == 0) {
        float t2 = red[0];
        for (int i = 1; i < 8; i++) t2 = fmaxf(t2, red[i]);
        bc[0] = t2;
    }
    __syncthreads();
    float e = expf(x - bc[0]);
#pragma unroll
    for (int o = 16; o > 0; o >>= 1) e += __shfl_xor_sync(0xffffffffu, e, o);
    __syncthreads();
    if (lane == 0) red[wid] = e;
    int tv = tgt[b * SXC + s];
    if (c == tv) tval = x;
    __syncthreads();
    if (c == 0) {
        float t2 = 0.0f;
        for (int i = 0; i < 8; i++) t2 += red[i];
        float lse = bc[0] + logf(t2);
        g_nll[bs] = lse - tval;
    }
}

// ---------------- deterministic final mean -----------------------------------
__global__ void reduce_kernel(float* __restrict__ out) {
    __shared__ float sh[1024];
    int t = threadIdx.x;
    float s = 0.0f;
    for (int i = t; i < BXC * SXC; i += 1024) s += g_nll[i];
    sh[t] = s;
    __syncthreads();
    for (int o = 512; o > 0; o >>= 1) {
        if (t < o) sh[t] += sh[t + o];
        __syncthreads();
    }
    if (t == 0) out[0] = sh[0] / (float)(BXC * SXC);
}

// ---------------- host orchestration -----------------------------------------
extern "C" void kernel_launch(void* const* d_in, const int* in_sizes, int n_in,
                              void* d_out, int out_size) {
    const int*   inp   = (const int*)d_in[0];
    const int*   tgt   = (const int*)d_in[1];
    const float* emb   = (const float*)d_in[2];
    const float* w0s   = (const float*)d_in[3];
    const float* w1s   = (const float*)d_in[4];
    const float* w2s   = (const float*)d_in[5];
    const float* out_w = (const float*)d_in[6];
    const float* out_b = (const float*)d_in[7];
    float* out = (float*)d_out;

    float *ph, *py1, *py2, *pds, *pstr, *plog;
    uint32_t *pw0, *pw3, *pw2, *pwL;
    cudaGetSymbolAddress((void**)&ph,  g_h);
    cudaGetSymbolAddress((void**)&py1, g_y1);
    cudaGetSymbolAddress((void**)&py2, g_y2);
    cudaGetSymbolAddress((void**)&pds, g_ds3);
    cudaGetSymbolAddress((void**)&pstr, g_str);
    cudaGetSymbolAddress((void**)&plog, g_log);
    cudaGetSymbolAddress((void**)&pw0, g_wp0);
    cudaGetSymbolAddress((void**)&pw3, g_wp3);
    cudaGetSymbolAddress((void**)&pw2, g_wp2);
    cudaGetSymbolAddress((void**)&pwL, g_wpL);

    const int SM_T3 = (2 * (128 * 52) + 2 * (16 * 136)) * 4;   // 70656
    const int SM_T1 = (2 * (128 * 20) + 2 * (16 * 136)) * 4;   // 37888

    cudaFuncSetAttribute((const void*)mmbf<1, true,  false, true>,
                         cudaFuncAttributeMaxDynamicSharedMemorySize, SM_T1);
    cudaFuncSetAttribute((const void*)mmbf<3, true,  false, false>,
                         cudaFuncAttributeMaxDynamicSharedMemorySize, SM_T3);
    cudaFuncSetAttribute((const void*)mmbf<1, false, false, false>,
                         cudaFuncAttributeMaxDynamicSharedMemorySize, SM_T1);
    cudaFuncSetAttribute((const void*)mmbf<1, false, true,  false>,
                         cudaFuncAttributeMaxDynamicSharedMemorySize, SM_T1);

    // ---- launch 1: all weight packs + fe ----
    {
        int total = 6*IXC*3*(IXC/2) + 6*IXC*(FXC/2) + 6*FXC*(IXC/2) + CXC*FXC + FXC;
        pack_all<<<(total + 255) / 256, 256>>>(w1s, w0s, w2s, out_w);
    }
    // ---- launch 2: embedding ----
    {
        size_t n = (size_t)BXC * FXC * SXC;
        embed_kernel<<<(unsigned)((n + 255) / 256), 256>>>(inp, emb);
    }

    const size_t AzS3 = (size_t)IXC * 3 * (IXC/2);
    const size_t AzS2 = (size_t)FXC * (IXC/2);

    for (int l = 0; l < LXC; ++l) {
        const uint32_t* W0 = pw0 + (size_t)l * 3 * IXC * (FXC/2);
        const uint32_t* W3 = pw3 + (size_t)l * 3 * AzS3;
        const uint32_t* W2 = pw2 + (size_t)l * 3 * AzS2;

        // conv0: all 3 branches merged, M = 3072, Y split to [branch][b][i][s]
        dim3 grid0(SXC / 128, (3 * IXC) / 128, BXC);            // 16 x 24 x 2
        mmbf<1, true, false, true><<<grid0, 256, SM_T1>>>(
            W0, ph, py1, nullptr, 3 * IXC, FXC, SXC, FXC/2, 0);
        // conv1: causal k=3, z-batched over branch*B + b
        dim3 grid1(SXC / 128, IXC / 128, 3 * BXC);              // 16 x 8 x 6
        mmbf<3, true, false, false><<<grid1, 256, SM_T3>>>(
            W3, py1, py2, nullptr, IXC, IXC, SXC, 3 * (IXC/2), AzS3);
        // conv2: z-batched, writes [branch][b][f][s] into g_ds3
        dim3 grid2(SXC / 128, FXC / 128, 3 * BXC);              // 16 x 4 x 6
        mmbf<1, false, false, false><<<grid2, 256, SM_T1>>>(
            W2, py2, pds, nullptr, FXC, IXC, SXC, IXC/2, AzS2);

        dim3 gridCB(SXC / 64, BXC);
        if (l == LXC - 1) combine2<true><<<gridCB, 256>>>();
        else              combine2<false><<<gridCB, 256>>>();
    }

    {
        dim3 gridC(SXC / 128, CXC / 128, BXC);                  // 16 x 2 x 2
        mmbf<1, false, true, false><<<gridC, 256, SM_T1>>>(
            pwL, pstr, plog, out_b, CXC, 2 * FXC, SXC, FXC, 0);
    }
    nll_kernel<<<BXC * SXC, 256>>>(tgt);
    reduce_kernel<<<1, 1024>>>(out);
}